// round 2
// baseline (speedup 1.0000x reference)
#include <cuda_runtime.h>
#include <cstdint>
#include <cstddef>

// Shapes fixed by the dataset: x[8,2048,1024] fp32, Wk/Wq/Wv[1024,64] fp32,
// out[8,2048,64] fp32.
#define B_DIM 8
#define T_DIM 2048
#define E_DIM 1024
#define H_DIM 64
#define M_DIM (B_DIM * T_DIM)   // 16384

// Scratch for q/k/v projections (device globals: allocation-free).
__device__ float g_q[M_DIM * H_DIM];
__device__ float g_k[M_DIM * H_DIM];
__device__ float g_v[M_DIM * H_DIM];

// ---------------- packed f32x2 helpers (sm_100+) ----------------
__device__ __forceinline__ unsigned long long pack2(float lo, float hi) {
    unsigned long long r;
    asm("mov.b64 %0, {%1, %2};" : "=l"(r) : "f"(lo), "f"(hi));
    return r;
}
__device__ __forceinline__ void unpack2(unsigned long long v, float& lo, float& hi) {
    asm("mov.b64 {%0, %1}, %2;" : "=f"(lo), "=f"(hi) : "l"(v));
}
__device__ __forceinline__ void fma2(unsigned long long& d, unsigned long long a,
                                     unsigned long long b) {
    asm("fma.rn.f32x2 %0, %1, %2, %0;" : "+l"(d) : "l"(a), "l"(b));
}
__device__ __forceinline__ void mul2(unsigned long long& d, unsigned long long a,
                                     unsigned long long b) {
    asm("mul.rn.f32x2 %0, %1, %2;" : "=l"(d) : "l"(a), "l"(b));
}

// ================= Kernel 1: fused q/k/v projection =================
// out[m, n] = sum_e x[m, e] * W[e, n];  M=16384, E=1024, N=64.
// Block: 64x64 output tile, 256 threads (16x16), 4x4 micro-tile, BK=32.
// grid.y selects which of Wk/Wq/Wv (and matching scratch output).
__global__ __launch_bounds__(256) void proj_kernel(
    const float* __restrict__ x,
    const float* __restrict__ Wk,
    const float* __restrict__ Wq,
    const float* __restrict__ Wv)
{
    __shared__ float xs[64][32];
    __shared__ float ws[32][64];

    const float* W;
    float* out;
    if (blockIdx.y == 0)      { W = Wk; out = g_k; }
    else if (blockIdx.y == 1) { W = Wq; out = g_q; }
    else                      { W = Wv; out = g_v; }

    const int m0 = blockIdx.x * 64;
    const int tid = threadIdx.x;
    const int tx = tid & 15;
    const int ty = tid >> 4;

    // load mappings
    const int xr = tid >> 3;          // 0..31
    const int xc = (tid & 7) * 4;     // 0..28
    const int wr = tid >> 4;          // 0..15
    const int wc = (tid & 15) * 4;    // 0..60

    unsigned long long acc0[4], acc1[4];
#pragma unroll
    for (int i = 0; i < 4; i++) { acc0[i] = 0ULL; acc1[i] = 0ULL; }

    for (int e0 = 0; e0 < E_DIM; e0 += 32) {
        __syncthreads();
        *(float4*)&xs[xr][xc] =
            *(const float4*)&x[(size_t)(m0 + xr) * E_DIM + e0 + xc];
        *(float4*)&xs[xr + 32][xc] =
            *(const float4*)&x[(size_t)(m0 + xr + 32) * E_DIM + e0 + xc];
        *(float4*)&ws[wr][wc] =
            *(const float4*)&W[(size_t)(e0 + wr) * H_DIM + wc];
        *(float4*)&ws[wr + 16][wc] =
            *(const float4*)&W[(size_t)(e0 + wr + 16) * H_DIM + wc];
        __syncthreads();

#pragma unroll 8
        for (int kk = 0; kk < 32; kk++) {
            ulonglong2 bv = *(const ulonglong2*)&ws[kk][tx * 4];
#pragma unroll
            for (int i = 0; i < 4; i++) {
                float a = xs[ty * 4 + i][kk];
                unsigned long long aa = pack2(a, a);
                fma2(acc0[i], aa, bv.x);
                fma2(acc1[i], aa, bv.y);
            }
        }
    }

#pragma unroll
    for (int i = 0; i < 4; i++) {
        float r0, r1, r2, r3;
        unpack2(acc0[i], r0, r1);
        unpack2(acc1[i], r2, r3);
        float4 r = make_float4(r0, r1, r2, r3);
        *(float4*)&out[(size_t)(m0 + ty * 4 + i) * H_DIM + tx * 4] = r;
    }
}

// ================= Kernel 2: flash attention (causal) =================
// grid: (T/64 q-tiles, B). Block: 256 threads (16x16), 4x4 micro-tiles.
// Online softmax; P tile aliased onto the K smem buffer.
// Dynamic smem layout (floats):
//   sQ : 64*64            (offset 0)
//   sKP: 64*65  (padded)  (offset 4096)
//   sV : 64*64            (offset 4096+4160=8256)
// Total 12352 floats = 49408 bytes (needs opt-in dynamic smem).
#define ATTN_SMEM_BYTES (12352 * 4)

__global__ __launch_bounds__(256) void attn_kernel(float* __restrict__ out)
{
    extern __shared__ float smem[];
    float* sQ  = smem;              // [64][64]
    float* sKP = smem + 4096;       // [64][65]
    float* sV  = smem + 8256;       // [64][64]
#define SQ(r, c)  sQ[(r) * 64 + (c)]
#define SKP(r, c) sKP[(r) * 65 + (c)]
#define SV(r, c)  sV[(r) * 64 + (c)]

    const int b = blockIdx.y;
    const int qi = blockIdx.x;
    const int q0 = qi * 64;
    const int tid = threadIdx.x;
    const int tx = tid & 15;
    const int ty = tid >> 4;

    const float* qg = g_q + ((size_t)b * T_DIM + q0) * H_DIM;
    const float* kg = g_k + (size_t)b * T_DIM * H_DIM;
    const float* vg = g_v + (size_t)b * T_DIM * H_DIM;

    // Load Q tile, pre-scaled by H^-0.5 = 0.125
    {
        const int rr = tid >> 4;
        const int cc = (tid & 15) * 4;
#pragma unroll
        for (int p = 0; p < 4; p++) {
            int r = p * 16 + rr;
            float4 t = *(const float4*)&qg[(size_t)r * H_DIM + cc];
            SQ(r, cc + 0) = t.x * 0.125f;
            SQ(r, cc + 1) = t.y * 0.125f;
            SQ(r, cc + 2) = t.z * 0.125f;
            SQ(r, cc + 3) = t.w * 0.125f;
        }
    }

    float m_i[4], l_i[4];
    unsigned long long o0[4], o1[4];
#pragma unroll
    for (int i = 0; i < 4; i++) {
        m_i[i] = -1e30f; l_i[i] = 0.0f; o0[i] = 0ULL; o1[i] = 0ULL;
    }

    for (int ki = 0; ki <= qi; ki++) {
        const int n0 = ki * 64;
        __syncthreads();   // previous P/V reads done (and Q stores on iter 0)
        {
            const int rr = tid >> 4;
            const int cc = (tid & 15) * 4;
#pragma unroll
            for (int p = 0; p < 4; p++) {
                int r = p * 16 + rr;
                float4 kv = *(const float4*)&kg[(size_t)(n0 + r) * H_DIM + cc];
                SKP(r, cc + 0) = kv.x;
                SKP(r, cc + 1) = kv.y;
                SKP(r, cc + 2) = kv.z;
                SKP(r, cc + 3) = kv.w;
                *(float4*)&SV(r, cc) =
                    *(const float4*)&vg[(size_t)(n0 + r) * H_DIM + cc];
            }
        }
        __syncthreads();

        // ---- S = Q K^T (pre-scaled) ----
        float s[4][4];
#pragma unroll
        for (int i = 0; i < 4; i++)
#pragma unroll
            for (int j = 0; j < 4; j++) s[i][j] = 0.0f;

#pragma unroll 16
        for (int kk = 0; kk < 64; kk++) {
            float a0 = SQ(ty * 4 + 0, kk);
            float a1 = SQ(ty * 4 + 1, kk);
            float a2 = SQ(ty * 4 + 2, kk);
            float a3 = SQ(ty * 4 + 3, kk);
            float b0 = SKP(tx * 4 + 0, kk);
            float b1 = SKP(tx * 4 + 1, kk);
            float b2 = SKP(tx * 4 + 2, kk);
            float b3 = SKP(tx * 4 + 3, kk);
            s[0][0] += a0 * b0; s[0][1] += a0 * b1; s[0][2] += a0 * b2; s[0][3] += a0 * b3;
            s[1][0] += a1 * b0; s[1][1] += a1 * b1; s[1][2] += a1 * b2; s[1][3] += a1 * b3;
            s[2][0] += a2 * b0; s[2][1] += a2 * b1; s[2][2] += a2 * b2; s[2][3] += a2 * b3;
            s[3][0] += a3 * b0; s[3][1] += a3 * b1; s[3][2] += a3 * b2; s[3][3] += a3 * b3;
        }
        __syncthreads();   // all K reads done before overwriting sKP with P

        // ---- online softmax (rows across tx via shfl) + write P ----
#pragma unroll
        for (int i = 0; i < 4; i++) {
            if (ki == qi) {
                int qrow = q0 + ty * 4 + i;
#pragma unroll
                for (int j = 0; j < 4; j++)
                    if (n0 + tx * 4 + j > qrow) s[i][j] = -1e30f;
            }
            float rm = fmaxf(fmaxf(s[i][0], s[i][1]), fmaxf(s[i][2], s[i][3]));
            rm = fmaxf(rm, __shfl_xor_sync(0xffffffffu, rm, 1));
            rm = fmaxf(rm, __shfl_xor_sync(0xffffffffu, rm, 2));
            rm = fmaxf(rm, __shfl_xor_sync(0xffffffffu, rm, 4));
            rm = fmaxf(rm, __shfl_xor_sync(0xffffffffu, rm, 8));
            float m_new = fmaxf(m_i[i], rm);
            float alpha = __expf(m_i[i] - m_new);
            m_i[i] = m_new;

            float rs = 0.0f;
#pragma unroll
            for (int j = 0; j < 4; j++) {
                s[i][j] = __expf(s[i][j] - m_new);
                rs += s[i][j];
            }
            rs += __shfl_xor_sync(0xffffffffu, rs, 1);
            rs += __shfl_xor_sync(0xffffffffu, rs, 2);
            rs += __shfl_xor_sync(0xffffffffu, rs, 4);
            rs += __shfl_xor_sync(0xffffffffu, rs, 8);
            l_i[i] = l_i[i] * alpha + rs;

            unsigned long long av = pack2(alpha, alpha);
            mul2(o0[i], o0[i], av);
            mul2(o1[i], o1[i], av);

            SKP(ty * 4 + i, tx * 4 + 0) = s[i][0];
            SKP(ty * 4 + i, tx * 4 + 1) = s[i][1];
            SKP(ty * 4 + i, tx * 4 + 2) = s[i][2];
            SKP(ty * 4 + i, tx * 4 + 3) = s[i][3];
        }
        __syncthreads();   // P visible to all

        // ---- O += P V (packed f32x2 along h) ----
#pragma unroll 8
        for (int kk = 0; kk < 64; kk++) {
            ulonglong2 bv = *(const ulonglong2*)&SV(kk, tx * 4);
#pragma unroll
            for (int i = 0; i < 4; i++) {
                float a = SKP(ty * 4 + i, kk);
                unsigned long long aa = pack2(a, a);
                fma2(o0[i], aa, bv.x);
                fma2(o1[i], aa, bv.y);
            }
        }
    }

    // ---- epilogue: O / l ----
#pragma unroll
    for (int i = 0; i < 4; i++) {
        float inv = 1.0f / l_i[i];
        float r0, r1, r2, r3;
        unpack2(o0[i], r0, r1);
        unpack2(o1[i], r2, r3);
        float4 r = make_float4(r0 * inv, r1 * inv, r2 * inv, r3 * inv);
        *(float4*)&out[((size_t)b * T_DIM + q0 + ty * 4 + i) * H_DIM + tx * 4] = r;
    }
}

extern "C" void kernel_launch(void* const* d_in, const int* in_sizes, int n_in,
                              void* d_out, int out_size)
{
    (void)in_sizes; (void)n_in; (void)out_size;
    const float* x  = (const float*)d_in[0];
    const float* Wk = (const float*)d_in[1];
    const float* Wq = (const float*)d_in[2];
    const float* Wv = (const float*)d_in[3];
    float* out = (float*)d_out;

    // Opt-in to >48KB dynamic smem for the attention kernel (capture-safe,
    // idempotent, no allocation).
    static bool attr_set = false;
    if (!attr_set) {
        cudaFuncSetAttribute(attn_kernel,
                             cudaFuncAttributeMaxDynamicSharedMemorySize,
                             ATTN_SMEM_BYTES);
        attr_set = true;
    }

    proj_kernel<<<dim3(M_DIM / 64, 3), 256>>>(x, Wk, Wq, Wv);
    attn_kernel<<<dim3(T_DIM / 64, B_DIM), 256, ATTN_SMEM_BYTES>>>(out);
}

// round 3
// speedup vs baseline: 1.1219x; 1.1219x over previous
#include <cuda_runtime.h>
#include <cstdint>
#include <cstddef>

// Shapes fixed by the dataset.
#define B_DIM 8
#define T_DIM 2048
#define E_DIM 1024
#define H_DIM 64
#define M_DIM (B_DIM * T_DIM)   // 16384
#define NQT   (T_DIM / 64)      // 32 q-tiles per batch
#define MAXC  8                 // max k-chunks per q-tile
#define CHUNKS_PER_B 144        // sum_{qi=0}^{31} (qi/4 + 1)

// Device-global scratch (allocation-free).
__device__ float g_q[M_DIM * H_DIM];
__device__ float g_k[M_DIM * H_DIM];
__device__ float g_v[M_DIM * H_DIM];
__device__ float g_pO[(size_t)B_DIM * NQT * MAXC * 64 * 64];  // 33.5 MB
__device__ float g_pm[B_DIM * NQT * MAXC * 64];
__device__ float g_pl[B_DIM * NQT * MAXC * 64];

typedef unsigned long long ull;

// ---------------- packed f32x2 helpers (sm_100+) ----------------
__device__ __forceinline__ ull pack2(float lo, float hi) {
    ull r;
    asm("mov.b64 %0, {%1, %2};" : "=l"(r) : "f"(lo), "f"(hi));
    return r;
}
__device__ __forceinline__ void unpack2(ull v, float& lo, float& hi) {
    asm("mov.b64 {%0, %1}, %2;" : "=f"(lo), "=f"(hi) : "l"(v));
}
__device__ __forceinline__ void fma2(ull& d, ull a, ull b) {
    asm("fma.rn.f32x2 %0, %1, %2, %0;" : "+l"(d) : "l"(a), "l"(b));
}
__device__ __forceinline__ void mul2(ull& d, ull a, ull b) {
    asm("mul.rn.f32x2 %0, %1, %2;" : "=l"(d) : "l"(a), "l"(b));
}

// ================= Kernel 1: fused q/k/v projection =================
// One x-tile (64 rows x BK=32) feeds all three W GEMMs.
// Block 256 = 16(tx) x 16(ty); micro-tile 4m x (3 x 4n); splatted-a smem.
__global__ __launch_bounds__(256) void proj_kernel(
    const float* __restrict__ x,
    const float* __restrict__ Wk,
    const float* __restrict__ Wq,
    const float* __restrict__ Wv)
{
    __shared__ ull   xs2[64][33];       // x values splatted {v,v}; padded
    __shared__ float ws[3][32][64];     // W tiles (k,q,v)

    const int m0 = blockIdx.x * 64;
    const int tid = threadIdx.x;
    const int tx = tid & 15;
    const int ty = tid >> 4;

    const int xr = tid >> 2;            // 0..63
    const int xc = (tid & 3) * 8;       // 0,8,16,24
    const int wr = tid >> 3;            // 0..31
    const int wc = (tid & 7) * 8;       // 0..56

    ull acc[3][4][2];
#pragma unroll
    for (int w = 0; w < 3; w++)
#pragma unroll
        for (int i = 0; i < 4; i++) { acc[w][i][0] = 0ULL; acc[w][i][1] = 0ULL; }

    for (int e0 = 0; e0 < E_DIM; e0 += 32) {
        __syncthreads();
        // x tile -> splatted smem
        {
            float4 v0 = *(const float4*)&x[(size_t)(m0 + xr) * E_DIM + e0 + xc];
            float4 v1 = *(const float4*)&x[(size_t)(m0 + xr) * E_DIM + e0 + xc + 4];
            xs2[xr][xc + 0] = pack2(v0.x, v0.x);
            xs2[xr][xc + 1] = pack2(v0.y, v0.y);
            xs2[xr][xc + 2] = pack2(v0.z, v0.z);
            xs2[xr][xc + 3] = pack2(v0.w, v0.w);
            xs2[xr][xc + 4] = pack2(v1.x, v1.x);
            xs2[xr][xc + 5] = pack2(v1.y, v1.y);
            xs2[xr][xc + 6] = pack2(v1.z, v1.z);
            xs2[xr][xc + 7] = pack2(v1.w, v1.w);
        }
        // W tiles
        *(float4*)&ws[0][wr][wc]     = *(const float4*)&Wk[(size_t)(e0 + wr) * H_DIM + wc];
        *(float4*)&ws[0][wr][wc + 4] = *(const float4*)&Wk[(size_t)(e0 + wr) * H_DIM + wc + 4];
        *(float4*)&ws[1][wr][wc]     = *(const float4*)&Wq[(size_t)(e0 + wr) * H_DIM + wc];
        *(float4*)&ws[1][wr][wc + 4] = *(const float4*)&Wq[(size_t)(e0 + wr) * H_DIM + wc + 4];
        *(float4*)&ws[2][wr][wc]     = *(const float4*)&Wv[(size_t)(e0 + wr) * H_DIM + wc];
        *(float4*)&ws[2][wr][wc + 4] = *(const float4*)&Wv[(size_t)(e0 + wr) * H_DIM + wc + 4];
        __syncthreads();

#pragma unroll 8
        for (int kk = 0; kk < 32; kk++) {
            ull a0 = xs2[ty * 4 + 0][kk];
            ull a1 = xs2[ty * 4 + 1][kk];
            ull a2 = xs2[ty * 4 + 2][kk];
            ull a3 = xs2[ty * 4 + 3][kk];
#pragma unroll
            for (int w = 0; w < 3; w++) {
                ulonglong2 bv = *(const ulonglong2*)&ws[w][kk][tx * 4];
                fma2(acc[w][0][0], a0, bv.x); fma2(acc[w][0][1], a0, bv.y);
                fma2(acc[w][1][0], a1, bv.x); fma2(acc[w][1][1], a1, bv.y);
                fma2(acc[w][2][0], a2, bv.x); fma2(acc[w][2][1], a2, bv.y);
                fma2(acc[w][3][0], a3, bv.x); fma2(acc[w][3][1], a3, bv.y);
            }
        }
    }

    // epilogue: k, q(pre-scaled by H^-0.5), v
#pragma unroll
    for (int w = 0; w < 3; w++) {
        float* out = (w == 0) ? g_k : (w == 1) ? g_q : g_v;
        float scale = (w == 1) ? 0.125f : 1.0f;
#pragma unroll
        for (int i = 0; i < 4; i++) {
            float r0, r1, r2, r3;
            unpack2(acc[w][i][0], r0, r1);
            unpack2(acc[w][i][1], r2, r3);
            float4 r = make_float4(r0 * scale, r1 * scale, r2 * scale, r3 * scale);
            *(float4*)&out[(size_t)(m0 + ty * 4 + i) * H_DIM + tx * 4] = r;
        }
    }
}

// ================= Kernel 2: split-K flash attention (causal) =================
// Grid (144, B): each CTA = one (qi, chunk) of <=4 k-tiles. Writes partial
// (O unnormalized, m, l) to scratch. Dual-kk f32x2: each 64-bit accumulator
// holds {even-kk partial sum, odd-kk partial sum}.
#define SSTR 66
#define ATTN_SMEM_BYTES (4 * 64 * SSTR * 4)   // sQ, sK, sVT, sP = 67584 B

__global__ __launch_bounds__(256, 2) void attn_kernel()
{
    extern __shared__ float sm[];
    float* sQ  = sm;                 // [64][66]
    float* sK  = sm + 64 * SSTR;     // [64][66]
    float* sVT = sm + 2 * 64 * SSTR; // [64][66]  V transposed: [h][t]
    float* sP  = sm + 3 * 64 * SSTR; // [64][66]

    const int tid = threadIdx.x;
    const int tx = tid & 15;
    const int ty = tid >> 4;
    const int b = blockIdx.y;

    // map flat chunk id -> (qi, c)
    int f = blockIdx.x;
    int qi = 0, pre = 0;
    while (pre + (qi / 4 + 1) <= f) { pre += qi / 4 + 1; qi++; }
    const int c = f - pre;
    const int nc = qi / 4 + 1;
    const int ntiles = qi + 1;
    const int base = ntiles / nc;
    const int rem = ntiles % nc;
    const int my_tiles = base + (c < rem ? 1 : 0);
    const int k_start = c * base + (c < rem ? c : rem);
    const int q0 = qi * 64;

    const float* qg = g_q + ((size_t)b * T_DIM + q0) * H_DIM;
    const float* kg = g_k + (size_t)b * T_DIM * H_DIM;
    const float* vg = g_v + (size_t)b * T_DIM * H_DIM;

    // load Q tile (already pre-scaled in proj)
    {
        const int rr = tid >> 4;
        const int cc = (tid & 15) * 4;
#pragma unroll
        for (int p = 0; p < 4; p++) {
            int r = p * 16 + rr;
            float4 t = *(const float4*)&qg[(size_t)r * H_DIM + cc];
            *(ull*)&sQ[r * SSTR + cc]     = pack2(t.x, t.y);
            *(ull*)&sQ[r * SSTR + cc + 2] = pack2(t.z, t.w);
        }
    }

    float m_i[4], l_i[4];
    ull O2[4][4];   // [i][j]: m = ty*4+i, h = tx*4+j; pair = {even,odd} kk sums
#pragma unroll
    for (int i = 0; i < 4; i++) {
        m_i[i] = -1e30f; l_i[i] = 0.0f;
#pragma unroll
        for (int j = 0; j < 4; j++) O2[i][j] = 0ULL;
    }

    for (int it = 0; it < my_tiles; it++) {
        const int ki = k_start + it;
        const int n0 = ki * 64;
        __syncthreads();
        {
            const int rr = tid >> 4;
            const int cc = (tid & 15) * 4;
#pragma unroll
            for (int p = 0; p < 4; p++) {
                int r = p * 16 + rr;
                float4 kv = *(const float4*)&kg[(size_t)(n0 + r) * H_DIM + cc];
                *(ull*)&sK[r * SSTR + cc]     = pack2(kv.x, kv.y);
                *(ull*)&sK[r * SSTR + cc + 2] = pack2(kv.z, kv.w);
                float4 vv = *(const float4*)&vg[(size_t)(n0 + r) * H_DIM + cc];
                sVT[(cc + 0) * SSTR + r] = vv.x;
                sVT[(cc + 1) * SSTR + r] = vv.y;
                sVT[(cc + 2) * SSTR + r] = vv.z;
                sVT[(cc + 3) * SSTR + r] = vv.w;
            }
        }
        __syncthreads();

        // ---- S = Q K^T : dual-kk f32x2 ----
        ull sa[4][4];
#pragma unroll
        for (int i = 0; i < 4; i++)
#pragma unroll
            for (int j = 0; j < 4; j++) sa[i][j] = 0ULL;

#pragma unroll 8
        for (int kk = 0; kk < 64; kk += 2) {
            ull a0 = *(const ull*)&sQ[(ty * 4 + 0) * SSTR + kk];
            ull a1 = *(const ull*)&sQ[(ty * 4 + 1) * SSTR + kk];
            ull a2 = *(const ull*)&sQ[(ty * 4 + 2) * SSTR + kk];
            ull a3 = *(const ull*)&sQ[(ty * 4 + 3) * SSTR + kk];
            ull b0 = *(const ull*)&sK[(tx * 4 + 0) * SSTR + kk];
            ull b1 = *(const ull*)&sK[(tx * 4 + 1) * SSTR + kk];
            ull b2 = *(const ull*)&sK[(tx * 4 + 2) * SSTR + kk];
            ull b3 = *(const ull*)&sK[(tx * 4 + 3) * SSTR + kk];
            fma2(sa[0][0], a0, b0); fma2(sa[0][1], a0, b1); fma2(sa[0][2], a0, b2); fma2(sa[0][3], a0, b3);
            fma2(sa[1][0], a1, b0); fma2(sa[1][1], a1, b1); fma2(sa[1][2], a1, b2); fma2(sa[1][3], a1, b3);
            fma2(sa[2][0], a2, b0); fma2(sa[2][1], a2, b1); fma2(sa[2][2], a2, b2); fma2(sa[2][3], a2, b3);
            fma2(sa[3][0], a3, b0); fma2(sa[3][1], a3, b1); fma2(sa[3][2], a3, b2); fma2(sa[3][3], a3, b3);
        }
        float s[4][4];
#pragma unroll
        for (int i = 0; i < 4; i++)
#pragma unroll
            for (int j = 0; j < 4; j++) {
                float lo, hi; unpack2(sa[i][j], lo, hi);
                s[i][j] = lo + hi;
            }

        // ---- online softmax ----
#pragma unroll
        for (int i = 0; i < 4; i++) {
            if (ki == qi) {
                int qrow = q0 + ty * 4 + i;
#pragma unroll
                for (int j = 0; j < 4; j++)
                    if (n0 + tx * 4 + j > qrow) s[i][j] = -1e30f;
            }
            float rm = fmaxf(fmaxf(s[i][0], s[i][1]), fmaxf(s[i][2], s[i][3]));
            rm = fmaxf(rm, __shfl_xor_sync(0xffffffffu, rm, 1));
            rm = fmaxf(rm, __shfl_xor_sync(0xffffffffu, rm, 2));
            rm = fmaxf(rm, __shfl_xor_sync(0xffffffffu, rm, 4));
            rm = fmaxf(rm, __shfl_xor_sync(0xffffffffu, rm, 8));
            float m_new = fmaxf(m_i[i], rm);
            float alpha = __expf(m_i[i] - m_new);
            m_i[i] = m_new;

            float rs = 0.0f;
#pragma unroll
            for (int j = 0; j < 4; j++) {
                s[i][j] = __expf(s[i][j] - m_new);
                rs += s[i][j];
            }
            rs += __shfl_xor_sync(0xffffffffu, rs, 1);
            rs += __shfl_xor_sync(0xffffffffu, rs, 2);
            rs += __shfl_xor_sync(0xffffffffu, rs, 4);
            rs += __shfl_xor_sync(0xffffffffu, rs, 8);
            l_i[i] = l_i[i] * alpha + rs;

            ull av = pack2(alpha, alpha);
            mul2(O2[i][0], O2[i][0], av);
            mul2(O2[i][1], O2[i][1], av);
            mul2(O2[i][2], O2[i][2], av);
            mul2(O2[i][3], O2[i][3], av);

            *(ull*)&sP[(ty * 4 + i) * SSTR + tx * 4]     = pack2(s[i][0], s[i][1]);
            *(ull*)&sP[(ty * 4 + i) * SSTR + tx * 4 + 2] = pack2(s[i][2], s[i][3]);
        }
        __syncthreads();

        // ---- O += P V : dual-kk f32x2 (V transposed in smem) ----
#pragma unroll 8
        for (int kk = 0; kk < 64; kk += 2) {
            ull a0 = *(const ull*)&sP[(ty * 4 + 0) * SSTR + kk];
            ull a1 = *(const ull*)&sP[(ty * 4 + 1) * SSTR + kk];
            ull a2 = *(const ull*)&sP[(ty * 4 + 2) * SSTR + kk];
            ull a3 = *(const ull*)&sP[(ty * 4 + 3) * SSTR + kk];
            ull b0 = *(const ull*)&sVT[(tx * 4 + 0) * SSTR + kk];
            ull b1 = *(const ull*)&sVT[(tx * 4 + 1) * SSTR + kk];
            ull b2 = *(const ull*)&sVT[(tx * 4 + 2) * SSTR + kk];
            ull b3 = *(const ull*)&sVT[(tx * 4 + 3) * SSTR + kk];
            fma2(O2[0][0], a0, b0); fma2(O2[0][1], a0, b1); fma2(O2[0][2], a0, b2); fma2(O2[0][3], a0, b3);
            fma2(O2[1][0], a1, b0); fma2(O2[1][1], a1, b1); fma2(O2[1][2], a1, b2); fma2(O2[1][3], a1, b3);
            fma2(O2[2][0], a2, b0); fma2(O2[2][1], a2, b1); fma2(O2[2][2], a2, b2); fma2(O2[2][3], a2, b3);
            fma2(O2[3][0], a3, b0); fma2(O2[3][1], a3, b1); fma2(O2[3][2], a3, b2); fma2(O2[3][3], a3, b3);
        }
    }

    // ---- write partial (unnormalized O, m, l) ----
    const size_t pb = (size_t)(b * NQT + qi) * MAXC + c;
    float* pO = g_pO + pb * 4096;
#pragma unroll
    for (int i = 0; i < 4; i++) {
        int row = ty * 4 + i;
        float4 r;
        { float lo, hi; unpack2(O2[i][0], lo, hi); r.x = lo + hi; }
        { float lo, hi; unpack2(O2[i][1], lo, hi); r.y = lo + hi; }
        { float lo, hi; unpack2(O2[i][2], lo, hi); r.z = lo + hi; }
        { float lo, hi; unpack2(O2[i][3], lo, hi); r.w = lo + hi; }
        *(float4*)&pO[row * 64 + tx * 4] = r;
        if (tx == 0) {
            g_pm[pb * 64 + row] = m_i[i];
            g_pl[pb * 64 + row] = l_i[i];
        }
    }
}

// ================= Kernel 3: combine partials =================
// Grid (NQT, B), 256 threads; thread handles one row x 16 cols.
__global__ __launch_bounds__(256) void combine_kernel(float* __restrict__ out)
{
    const int qi = blockIdx.x;
    const int b = blockIdx.y;
    const int nc = qi / 4 + 1;
    const int tid = threadIdx.x;
    const int row = tid >> 2;
    const int cg = (tid & 3) * 16;

    const size_t pb0 = (size_t)(b * NQT + qi) * MAXC;

    float mg = -1e30f;
    for (int c = 0; c < nc; c++)
        mg = fmaxf(mg, g_pm[(pb0 + c) * 64 + row]);

    float lg = 0.0f;
    for (int c = 0; c < nc; c++)
        lg += g_pl[(pb0 + c) * 64 + row] * __expf(g_pm[(pb0 + c) * 64 + row] - mg);
    float inv = 1.0f / lg;

    float4 acc[4];
#pragma unroll
    for (int g = 0; g < 4; g++) acc[g] = make_float4(0.f, 0.f, 0.f, 0.f);

    for (int c = 0; c < nc; c++) {
        float w = __expf(g_pm[(pb0 + c) * 64 + row] - mg);
        const float* pO = g_pO + (pb0 + c) * 4096 + row * 64 + cg;
#pragma unroll
        for (int g = 0; g < 4; g++) {
            float4 t = *(const float4*)&pO[g * 4];
            acc[g].x += w * t.x; acc[g].y += w * t.y;
            acc[g].z += w * t.z; acc[g].w += w * t.w;
        }
    }

    float* o = out + ((size_t)b * T_DIM + qi * 64 + row) * H_DIM + cg;
#pragma unroll
    for (int g = 0; g < 4; g++) {
        float4 r = make_float4(acc[g].x * inv, acc[g].y * inv,
                               acc[g].z * inv, acc[g].w * inv);
        *(float4*)&o[g * 4] = r;
    }
}

extern "C" void kernel_launch(void* const* d_in, const int* in_sizes, int n_in,
                              void* d_out, int out_size)
{
    (void)in_sizes; (void)n_in; (void)out_size;
    const float* x  = (const float*)d_in[0];
    const float* Wk = (const float*)d_in[1];
    const float* Wq = (const float*)d_in[2];
    const float* Wv = (const float*)d_in[3];
    float* out = (float*)d_out;

    static bool attr_set = false;
    if (!attr_set) {
        cudaFuncSetAttribute(attn_kernel,
                             cudaFuncAttributeMaxDynamicSharedMemorySize,
                             ATTN_SMEM_BYTES);
        attr_set = true;
    }

    proj_kernel<<<M_DIM / 64, 256>>>(x, Wk, Wq, Wv);
    attn_kernel<<<dim3(CHUNKS_PER_B, B_DIM), 256, ATTN_SMEM_BYTES>>>();
    combine_kernel<<<dim3(NQT, B_DIM), 256>>>(out);
}

// round 5
// speedup vs baseline: 1.5596x; 1.3902x over previous
#include <cuda_runtime.h>
#include <cuda_bf16.h>
#include <cstdint>
#include <cstddef>

// Shapes fixed by the dataset.
#define B_DIM 8
#define T_DIM 2048
#define E_DIM 1024
#define H_DIM 64
#define M_DIM (B_DIM * T_DIM)   // 16384
#define NQT   (T_DIM / 64)      // 32 q-tiles per batch
#define MAXC  8
#define CHUNKS_PER_B 144        // sum_{qi=0}^{31} (qi/4 + 1)

// Device-global scratch (allocation-free).
__device__ float g_q[M_DIM * H_DIM];
__device__ float g_k[M_DIM * H_DIM];
__device__ float g_v[M_DIM * H_DIM];
__device__ float g_pO[(size_t)B_DIM * NQT * MAXC * 64 * 64];
__device__ float g_pm[B_DIM * NQT * MAXC * 64];
__device__ float g_pl[B_DIM * NQT * MAXC * 64];
// W transposed + bf16-split: [3][64(n)][1024(e)]  (row n contiguous in e = B col-major)
__device__ __nv_bfloat16 g_wt_hi[3 * 64 * 1024];
__device__ __nv_bfloat16 g_wt_lo[3 * 64 * 1024];

typedef unsigned long long ull;

// ---------------- packed f32x2 helpers (sm_100+, base-target legal) --------
__device__ __forceinline__ ull pack2(float lo, float hi) {
    ull r; asm("mov.b64 %0, {%1, %2};" : "=l"(r) : "f"(lo), "f"(hi)); return r;
}
__device__ __forceinline__ void unpack2(ull v, float& lo, float& hi) {
    asm("mov.b64 {%0, %1}, %2;" : "=f"(lo), "=f"(hi) : "l"(v));
}
__device__ __forceinline__ void fma2(ull& d, ull a, ull b) {
    asm("fma.rn.f32x2 %0, %1, %2, %0;" : "+l"(d) : "l"(a), "l"(b));
}
__device__ __forceinline__ void mul2(ull& d, ull a, ull b) {
    asm("mul.rn.f32x2 %0, %1, %2;" : "=l"(d) : "l"(a), "l"(b));
}

// ---------------- warp MMA helpers (sm_80+ features, base-target legal) ----
__device__ __forceinline__ uint32_t smem_u32(const void* p) {
    uint32_t a;
    asm("{ .reg .u64 t; cvta.to.shared.u64 t, %1; cvt.u32.u64 %0, t; }"
        : "=r"(a) : "l"(p));
    return a;
}
#define LDSM_X4(r0, r1, r2, r3, a)                                             \
    asm volatile("ldmatrix.sync.aligned.m8n8.x4.shared.b16 {%0,%1,%2,%3}, [%4];" \
                 : "=r"(r0), "=r"(r1), "=r"(r2), "=r"(r3) : "r"(a))
#define LDSM_X2(r0, r1, a)                                                     \
    asm volatile("ldmatrix.sync.aligned.m8n8.x2.shared.b16 {%0,%1}, [%2];"     \
                 : "=r"(r0), "=r"(r1) : "r"(a))
__device__ __forceinline__ void mma_bf16(float d[4], uint32_t a0, uint32_t a1,
                                         uint32_t a2, uint32_t a3,
                                         uint32_t b0, uint32_t b1) {
    asm volatile(
        "mma.sync.aligned.m16n8k16.row.col.f32.bf16.bf16.f32 "
        "{%0,%1,%2,%3}, {%4,%5,%6,%7}, {%8,%9}, {%0,%1,%2,%3};"
        : "+f"(d[0]), "+f"(d[1]), "+f"(d[2]), "+f"(d[3])
        : "r"(a0), "r"(a1), "r"(a2), "r"(a3), "r"(b0), "r"(b1));
}

// ================= Kernel 0: W transpose + bf16 split =================
__global__ __launch_bounds__(256) void prep_w_kernel(
    const float* __restrict__ Wk,
    const float* __restrict__ Wq,
    const float* __restrict__ Wv)
{
    int idx = (blockIdx.x * 256 + threadIdx.x) * 4;   // grid 192 covers 3*64*1024
    int w = idx >> 16;
    int r = idx & 65535;
    int n = r >> 10;
    int e = r & 1023;
    const float* W = (w == 0) ? Wk : (w == 1) ? Wq : Wv;
#pragma unroll
    for (int j = 0; j < 4; j++) {
        float v = W[(size_t)(e + j) * H_DIM + n];
        __nv_bfloat16 hi = __float2bfloat16(v);
        __nv_bfloat16 lo = __float2bfloat16(v - __bfloat162float(hi));
        g_wt_hi[idx + j] = hi;
        g_wt_lo[idx + j] = lo;
    }
}

// ================= Kernel 1: HMMA projection (Ootomo bf16x3) ===============
// Per CTA: M=64 rows, N=192 (k|q|v), K=1024 in 32 chunks of 32.
// 8 warps: warp (w&3) -> m-tile 16, (w>>2) -> n-half of 96 (12 n8-tiles).
// D += Ah*Bh + Ah*Bl + Al*Bh  (fp32 accum in registers).
#define A_STR 40   // bf16 row stride (80B: conflict-free ldmatrix)
#define B_STR 40

__global__ __launch_bounds__(256) void proj_mma_kernel(const float* __restrict__ x)
{
    __shared__ __nv_bfloat16 sA_hi[64 * A_STR];
    __shared__ __nv_bfloat16 sA_lo[64 * A_STR];
    __shared__ __nv_bfloat16 sB_hi[192 * B_STR];
    __shared__ __nv_bfloat16 sB_lo[192 * B_STR];

    const int tid = threadIdx.x;
    const int wid = tid >> 5;
    const int lane = tid & 31;
    const int m0 = blockIdx.x * 64;
    const int wm = (wid & 3) * 16;      // warp m-tile base (within CTA)
    const int wn = (wid >> 2) * 96;     // warp n-half base

    float acc[12][4];
#pragma unroll
    for (int nt = 0; nt < 12; nt++)
#pragma unroll
        for (int j = 0; j < 4; j++) acc[nt][j] = 0.0f;

    // ldmatrix per-lane base addresses
    const int amat = lane >> 3, ar = lane & 7;
    // A x4: mat0 rows0-7 k0 | mat1 rows8-15 k0 | mat2 rows0-7 k+8 | mat3 rows8-15 k+8
    const int a_row = (amat & 1) * 8 + ar;
    const int a_kblk = (amat >> 1) * 8;
    uint32_t ah_base = smem_u32(sA_hi) + ((wm + a_row) * A_STR + a_kblk) * 2;
    uint32_t al_base = smem_u32(sA_lo) + ((wm + a_row) * A_STR + a_kblk) * 2;
    // B x2: mat0 rows n0-7 k0 | mat1 rows n0-7 k+8   (lanes 0-15 supply addrs)
    const int b_row = lane & 7;
    const int b_kblk = ((lane >> 3) & 1) * 8;
    uint32_t bh_base = smem_u32(sB_hi) + ((wn + b_row) * B_STR + b_kblk) * 2;
    uint32_t bl_base = smem_u32(sB_lo) + ((wn + b_row) * B_STR + b_kblk) * 2;

    for (int ch = 0; ch < 32; ch++) {
        const int e0 = ch * 32;
        __syncthreads();
        // ---- A: x[64][32] fp32 -> bf16 hi/lo ----
#pragma unroll
        for (int it = 0; it < 2; it++) {
            int flat = it * 256 + tid;          // 0..511
            int row = flat >> 3;
            int c4 = flat & 7;
            float4 v = *(const float4*)&x[(size_t)(m0 + row) * E_DIM + e0 + c4 * 4];
            __nv_bfloat16 h0 = __float2bfloat16(v.x);
            __nv_bfloat16 h1 = __float2bfloat16(v.y);
            __nv_bfloat16 h2 = __float2bfloat16(v.z);
            __nv_bfloat16 h3 = __float2bfloat16(v.w);
            __nv_bfloat162 hp0; hp0.x = h0; hp0.y = h1;
            __nv_bfloat162 hp1; hp1.x = h2; hp1.y = h3;
            __nv_bfloat162 lp0;
            lp0.x = __float2bfloat16(v.x - __bfloat162float(h0));
            lp0.y = __float2bfloat16(v.y - __bfloat162float(h1));
            __nv_bfloat162 lp1;
            lp1.x = __float2bfloat16(v.z - __bfloat162float(h2));
            lp1.y = __float2bfloat16(v.w - __bfloat162float(h3));
            int off = row * A_STR + c4 * 4;
            *(__nv_bfloat162*)&sA_hi[off]     = hp0;
            *(__nv_bfloat162*)&sA_hi[off + 2] = hp1;
            *(__nv_bfloat162*)&sA_lo[off]     = lp0;
            *(__nv_bfloat162*)&sA_lo[off + 2] = lp1;
        }
        // ---- B: g_wt_{hi,lo}[n][e0..e0+31] -> smem rows ----
#pragma unroll
        for (int it = 0; it < 3; it++) {
            int flat = it * 256 + tid;          // 0..767
            int n = flat >> 2;                  // 0..191
            int u = flat & 3;                   // 8-bf16 group
            float4 vh = *(const float4*)&g_wt_hi[(size_t)n * 1024 + e0 + u * 8];
            float4 vl = *(const float4*)&g_wt_lo[(size_t)n * 1024 + e0 + u * 8];
            *(float4*)&sB_hi[n * B_STR + u * 8] = vh;
            *(float4*)&sB_lo[n * B_STR + u * 8] = vl;
        }
        __syncthreads();

#pragma unroll
        for (int ks = 0; ks < 2; ks++) {
            const int koff = ks * 16 * 2;       // bytes
            uint32_t ah0, ah1, ah2, ah3, al0, al1, al2, al3;
            LDSM_X4(ah0, ah1, ah2, ah3, ah_base + koff);
            LDSM_X4(al0, al1, al2, al3, al_base + koff);
#pragma unroll
            for (int nt = 0; nt < 12; nt++) {
                const int noff = nt * 8 * B_STR * 2;
                uint32_t bh0, bh1, bl0, bl1;
                LDSM_X2(bh0, bh1, bh_base + noff + koff);
                LDSM_X2(bl0, bl1, bl_base + noff + koff);
                mma_bf16(acc[nt], ah0, ah1, ah2, ah3, bh0, bh1);
                mma_bf16(acc[nt], ah0, ah1, ah2, ah3, bl0, bl1);
                mma_bf16(acc[nt], al0, al1, al2, al3, bh0, bh1);
            }
        }
    }

    // ---- epilogue: rows m0+wm+lane/4 (+8); cols wn + nt*8 + (lane%4)*2 ----
    const int r0 = m0 + wm + (lane >> 2);
#pragma unroll
    for (int nt = 0; nt < 12; nt++) {
        int nglob = wn + nt * 8 + (lane & 3) * 2;
        int wsel = nglob >> 6;
        int col = nglob & 63;
        float* out = (wsel == 0) ? g_k : (wsel == 1) ? g_q : g_v;
        float sc = (wsel == 1) ? 0.125f : 1.0f;
        float2 v0 = make_float2(acc[nt][0] * sc, acc[nt][1] * sc);
        float2 v1 = make_float2(acc[nt][2] * sc, acc[nt][3] * sc);
        *(float2*)&out[(size_t)r0 * H_DIM + col] = v0;
        *(float2*)&out[(size_t)(r0 + 8) * H_DIM + col] = v1;
    }
}

// ================= Kernel 2: split-K flash attention (causal, FMA) =========
#define SSTR 66
#define ATTN_SMEM_BYTES (4 * 64 * SSTR * 4)

__global__ __launch_bounds__(256, 2) void attn_kernel()
{
    extern __shared__ float smf[];
    float* sQ  = smf;
    float* sK  = smf + 64 * SSTR;
    float* sVT = smf + 2 * 64 * SSTR;
    float* sP  = smf + 3 * 64 * SSTR;

    const int tid = threadIdx.x;
    const int tx = tid & 15;
    const int ty = tid >> 4;
    const int b = blockIdx.y;

    int f = blockIdx.x;
    int qi = 0, pre = 0;
    while (pre + (qi / 4 + 1) <= f) { pre += qi / 4 + 1; qi++; }
    const int c = f - pre;
    const int nc = qi / 4 + 1;
    const int ntiles = qi + 1;
    const int base = ntiles / nc;
    const int rem = ntiles % nc;
    const int my_tiles = base + (c < rem ? 1 : 0);
    const int k_start = c * base + (c < rem ? c : rem);
    const int q0 = qi * 64;

    const float* qg = g_q + ((size_t)b * T_DIM + q0) * H_DIM;
    const float* kg = g_k + (size_t)b * T_DIM * H_DIM;
    const float* vg = g_v + (size_t)b * T_DIM * H_DIM;

    {
        const int rr = tid >> 4;
        const int cc = (tid & 15) * 4;
#pragma unroll
        for (int p = 0; p < 4; p++) {
            int r = p * 16 + rr;
            float4 t = *(const float4*)&qg[(size_t)r * H_DIM + cc];
            *(ull*)&sQ[r * SSTR + cc]     = pack2(t.x, t.y);
            *(ull*)&sQ[r * SSTR + cc + 2] = pack2(t.z, t.w);
        }
    }

    float m_i[4], l_i[4];
    ull O2[4][4];
#pragma unroll
    for (int i = 0; i < 4; i++) {
        m_i[i] = -1e30f; l_i[i] = 0.0f;
#pragma unroll
        for (int j = 0; j < 4; j++) O2[i][j] = 0ULL;
    }

    for (int it = 0; it < my_tiles; it++) {
        const int ki = k_start + it;
        const int n0 = ki * 64;
        __syncthreads();
        {
            const int rr = tid >> 4;
            const int cc = (tid & 15) * 4;
#pragma unroll
            for (int p = 0; p < 4; p++) {
                int r = p * 16 + rr;
                float4 kv = *(const float4*)&kg[(size_t)(n0 + r) * H_DIM + cc];
                *(ull*)&sK[r * SSTR + cc]     = pack2(kv.x, kv.y);
                *(ull*)&sK[r * SSTR + cc + 2] = pack2(kv.z, kv.w);
                float4 vv = *(const float4*)&vg[(size_t)(n0 + r) * H_DIM + cc];
                sVT[(cc + 0) * SSTR + r] = vv.x;
                sVT[(cc + 1) * SSTR + r] = vv.y;
                sVT[(cc + 2) * SSTR + r] = vv.z;
                sVT[(cc + 3) * SSTR + r] = vv.w;
            }
        }
        __syncthreads();

        ull sa[4][4];
#pragma unroll
        for (int i = 0; i < 4; i++)
#pragma unroll
            for (int j = 0; j < 4; j++) sa[i][j] = 0ULL;

#pragma unroll 8
        for (int kk = 0; kk < 64; kk += 2) {
            ull a0 = *(const ull*)&sQ[(ty * 4 + 0) * SSTR + kk];
            ull a1 = *(const ull*)&sQ[(ty * 4 + 1) * SSTR + kk];
            ull a2 = *(const ull*)&sQ[(ty * 4 + 2) * SSTR + kk];
            ull a3 = *(const ull*)&sQ[(ty * 4 + 3) * SSTR + kk];
            ull b0 = *(const ull*)&sK[(tx * 4 + 0) * SSTR + kk];
            ull b1 = *(const ull*)&sK[(tx * 4 + 1) * SSTR + kk];
            ull b2 = *(const ull*)&sK[(tx * 4 + 2) * SSTR + kk];
            ull b3 = *(const ull*)&sK[(tx * 4 + 3) * SSTR + kk];
            fma2(sa[0][0], a0, b0); fma2(sa[0][1], a0, b1); fma2(sa[0][2], a0, b2); fma2(sa[0][3], a0, b3);
            fma2(sa[1][0], a1, b0); fma2(sa[1][1], a1, b1); fma2(sa[1][2], a1, b2); fma2(sa[1][3], a1, b3);
            fma2(sa[2][0], a2, b0); fma2(sa[2][1], a2, b1); fma2(sa[2][2], a2, b2); fma2(sa[2][3], a2, b3);
            fma2(sa[3][0], a3, b0); fma2(sa[3][1], a3, b1); fma2(sa[3][2], a3, b2); fma2(sa[3][3], a3, b3);
        }
        float s[4][4];
#pragma unroll
        for (int i = 0; i < 4; i++)
#pragma unroll
            for (int j = 0; j < 4; j++) {
                float lo, hi; unpack2(sa[i][j], lo, hi);
                s[i][j] = lo + hi;
            }

#pragma unroll
        for (int i = 0; i < 4; i++) {
            if (ki == qi) {
                int qrow = q0 + ty * 4 + i;
#pragma unroll
                for (int j = 0; j < 4; j++)
                    if (n0 + tx * 4 + j > qrow) s[i][j] = -1e30f;
            }
            float rm = fmaxf(fmaxf(s[i][0], s[i][1]), fmaxf(s[i][2], s[i][3]));
            rm = fmaxf(rm, __shfl_xor_sync(0xffffffffu, rm, 1));
            rm = fmaxf(rm, __shfl_xor_sync(0xffffffffu, rm, 2));
            rm = fmaxf(rm, __shfl_xor_sync(0xffffffffu, rm, 4));
            rm = fmaxf(rm, __shfl_xor_sync(0xffffffffu, rm, 8));
            float m_new = fmaxf(m_i[i], rm);
            float alpha = __expf(m_i[i] - m_new);
            m_i[i] = m_new;

            float rs = 0.0f;
#pragma unroll
            for (int j = 0; j < 4; j++) {
                s[i][j] = __expf(s[i][j] - m_new);
                rs += s[i][j];
            }
            rs += __shfl_xor_sync(0xffffffffu, rs, 1);
            rs += __shfl_xor_sync(0xffffffffu, rs, 2);
            rs += __shfl_xor_sync(0xffffffffu, rs, 4);
            rs += __shfl_xor_sync(0xffffffffu, rs, 8);
            l_i[i] = l_i[i] * alpha + rs;

            ull av = pack2(alpha, alpha);
            mul2(O2[i][0], O2[i][0], av);
            mul2(O2[i][1], O2[i][1], av);
            mul2(O2[i][2], O2[i][2], av);
            mul2(O2[i][3], O2[i][3], av);

            *(ull*)&sP[(ty * 4 + i) * SSTR + tx * 4]     = pack2(s[i][0], s[i][1]);
            *(ull*)&sP[(ty * 4 + i) * SSTR + tx * 4 + 2] = pack2(s[i][2], s[i][3]);
        }
        __syncthreads();

#pragma unroll 8
        for (int kk = 0; kk < 64; kk += 2) {
            ull a0 = *(const ull*)&sP[(ty * 4 + 0) * SSTR + kk];
            ull a1 = *(const ull*)&sP[(ty * 4 + 1) * SSTR + kk];
            ull a2 = *(const ull*)&sP[(ty * 4 + 2) * SSTR + kk];
            ull a3 = *(const ull*)&sP[(ty * 4 + 3) * SSTR + kk];
            ull b0 = *(const ull*)&sVT[(tx * 4 + 0) * SSTR + kk];
            ull b1 = *(const ull*)&sVT[(tx * 4 + 1) * SSTR + kk];
            ull b2 = *(const ull*)&sVT[(tx * 4 + 2) * SSTR + kk];
            ull b3 = *(const ull*)&sVT[(tx * 4 + 3) * SSTR + kk];
            fma2(O2[0][0], a0, b0); fma2(O2[0][1], a0, b1); fma2(O2[0][2], a0, b2); fma2(O2[0][3], a0, b3);
            fma2(O2[1][0], a1, b0); fma2(O2[1][1], a1, b1); fma2(O2[1][2], a1, b2); fma2(O2[1][3], a1, b3);
            fma2(O2[2][0], a2, b0); fma2(O2[2][1], a2, b1); fma2(O2[2][2], a2, b2); fma2(O2[2][3], a2, b3);
            fma2(O2[3][0], a3, b0); fma2(O2[3][1], a3, b1); fma2(O2[3][2], a3, b2); fma2(O2[3][3], a3, b3);
        }
    }

    const size_t pb = (size_t)(b * NQT + qi) * MAXC + c;
    float* pO = g_pO + pb * 4096;
#pragma unroll
    for (int i = 0; i < 4; i++) {
        int row = ty * 4 + i;
        float4 r;
        { float lo, hi; unpack2(O2[i][0], lo, hi); r.x = lo + hi; }
        { float lo, hi; unpack2(O2[i][1], lo, hi); r.y = lo + hi; }
        { float lo, hi; unpack2(O2[i][2], lo, hi); r.z = lo + hi; }
        { float lo, hi; unpack2(O2[i][3], lo, hi); r.w = lo + hi; }
        *(float4*)&pO[row * 64 + tx * 4] = r;
        if (tx == 0) {
            g_pm[pb * 64 + row] = m_i[i];
            g_pl[pb * 64 + row] = l_i[i];
        }
    }
}

// ================= Kernel 3: combine partials =================
__global__ __launch_bounds__(256) void combine_kernel(float* __restrict__ out)
{
    const int qi = blockIdx.x;
    const int b = blockIdx.y;
    const int nc = qi / 4 + 1;
    const int tid = threadIdx.x;
    const int row = tid >> 2;
    const int cg = (tid & 3) * 16;

    const size_t pb0 = (size_t)(b * NQT + qi) * MAXC;

    float mg = -1e30f;
    for (int c = 0; c < nc; c++)
        mg = fmaxf(mg, g_pm[(pb0 + c) * 64 + row]);

    float lg = 0.0f;
    for (int c = 0; c < nc; c++)
        lg += g_pl[(pb0 + c) * 64 + row] * __expf(g_pm[(pb0 + c) * 64 + row] - mg);
    float inv = 1.0f / lg;

    float4 acc[4];
#pragma unroll
    for (int g = 0; g < 4; g++) acc[g] = make_float4(0.f, 0.f, 0.f, 0.f);

    for (int c = 0; c < nc; c++) {
        float w = __expf(g_pm[(pb0 + c) * 64 + row] - mg);
        const float* pO = g_pO + (pb0 + c) * 4096 + row * 64 + cg;
#pragma unroll
        for (int g = 0; g < 4; g++) {
            float4 t = *(const float4*)&pO[g * 4];
            acc[g].x += w * t.x; acc[g].y += w * t.y;
            acc[g].z += w * t.z; acc[g].w += w * t.w;
        }
    }

    float* o = out + ((size_t)b * T_DIM + qi * 64 + row) * H_DIM + cg;
#pragma unroll
    for (int g = 0; g < 4; g++) {
        float4 r = make_float4(acc[g].x * inv, acc[g].y * inv,
                               acc[g].z * inv, acc[g].w * inv);
        *(float4*)&o[g * 4] = r;
    }
}

extern "C" void kernel_launch(void* const* d_in, const int* in_sizes, int n_in,
                              void* d_out, int out_size)
{
    (void)in_sizes; (void)n_in; (void)out_size;
    const float* x  = (const float*)d_in[0];
    const float* Wk = (const float*)d_in[1];
    const float* Wq = (const float*)d_in[2];
    const float* Wv = (const float*)d_in[3];
    float* out = (float*)d_out;

    static bool attr_set = false;
    if (!attr_set) {
        cudaFuncSetAttribute(attn_kernel,
                             cudaFuncAttributeMaxDynamicSharedMemorySize,
                             ATTN_SMEM_BYTES);
        attr_set = true;
    }

    prep_w_kernel<<<192, 256>>>(Wk, Wq, Wv);
    proj_mma_kernel<<<M_DIM / 64, 256>>>(x);
    attn_kernel<<<dim3(CHUNKS_PER_B, B_DIM), 256, ATTN_SMEM_BYTES>>>();
    combine_kernel<<<dim3(NQT, B_DIM), 256>>>(out);
}

// round 6
// speedup vs baseline: 2.8205x; 1.8085x over previous
#include <cuda_runtime.h>
#include <cuda_bf16.h>
#include <cstdint>
#include <cstddef>

// Shapes fixed by the dataset.
#define B_DIM 8
#define T_DIM 2048
#define E_DIM 1024
#define H_DIM 64
#define M_DIM (B_DIM * T_DIM)   // 16384
#define NQT2  16                // 128-row q-tiles per batch
#define MAXC2 8
#define CH2_PER_B 72            // sum_{qi=0}^{15} ceil((2qi+2)/4)
#define QT 128

// Device-global scratch (allocation-free). q/k/v stored bf16 hi/lo (Ootomo split).
__device__ __nv_bfloat16 g_qh[M_DIM * H_DIM];
__device__ __nv_bfloat16 g_ql[M_DIM * H_DIM];
__device__ __nv_bfloat16 g_kh[M_DIM * H_DIM];
__device__ __nv_bfloat16 g_kl[M_DIM * H_DIM];
__device__ __nv_bfloat16 g_vh[M_DIM * H_DIM];
__device__ __nv_bfloat16 g_vl[M_DIM * H_DIM];
__device__ float g_pO[(size_t)B_DIM * NQT2 * MAXC2 * QT * H_DIM];  // 33.5 MB
__device__ float g_pm[B_DIM * NQT2 * MAXC2 * QT];
__device__ float g_pl[B_DIM * NQT2 * MAXC2 * QT];
// W transposed + bf16-split: [3][64(n)][1024(e)]
__device__ __nv_bfloat16 g_wt_hi[3 * 64 * 1024];
__device__ __nv_bfloat16 g_wt_lo[3 * 64 * 1024];

// ---------------- helpers ----------------
__device__ __forceinline__ uint32_t smem_u32(const void* p) {
    uint32_t a;
    asm("{ .reg .u64 t; cvta.to.shared.u64 t, %1; cvt.u32.u64 %0, t; }"
        : "=r"(a) : "l"(p));
    return a;
}
#define LDSM_X4(r0, r1, r2, r3, a)                                             \
    asm volatile("ldmatrix.sync.aligned.m8n8.x4.shared.b16 {%0,%1,%2,%3}, [%4];" \
                 : "=r"(r0), "=r"(r1), "=r"(r2), "=r"(r3) : "r"(a))
#define LDSM_X2(r0, r1, a)                                                     \
    asm volatile("ldmatrix.sync.aligned.m8n8.x2.shared.b16 {%0,%1}, [%2];"     \
                 : "=r"(r0), "=r"(r1) : "r"(a))
__device__ __forceinline__ void mma_bf16(float d[4], uint32_t a0, uint32_t a1,
                                         uint32_t a2, uint32_t a3,
                                         uint32_t b0, uint32_t b1) {
    asm volatile(
        "mma.sync.aligned.m16n8k16.row.col.f32.bf16.bf16.f32 "
        "{%0,%1,%2,%3}, {%4,%5,%6,%7}, {%8,%9}, {%0,%1,%2,%3};"
        : "+f"(d[0]), "+f"(d[1]), "+f"(d[2]), "+f"(d[3])
        : "r"(a0), "r"(a1), "r"(a2), "r"(a3), "r"(b0), "r"(b1));
}
// pack two fp32 -> bf16x2 (lo in low half)
__device__ __forceinline__ uint32_t cvt2(float hi, float lo) {
    uint32_t r;
    asm("cvt.rn.bf16x2.f32 %0, %1, %2;" : "=r"(r) : "f"(hi), "f"(lo));
    return r;
}
// residual pair: (hi,lo) minus bf16(hi,lo) packed -> bf16x2
__device__ __forceinline__ uint32_t resid2(uint32_t h, float hi, float lo) {
    float fl = __uint_as_float(h << 16);
    float fh = __uint_as_float(h & 0xFFFF0000u);
    return cvt2(hi - fh, lo - fl);
}

// ================= Kernel 0: W transpose + bf16 split =================
__global__ __launch_bounds__(256) void prep_w_kernel(
    const float* __restrict__ Wk,
    const float* __restrict__ Wq,
    const float* __restrict__ Wv)
{
    int idx = (blockIdx.x * 256 + threadIdx.x) * 4;
    int w = idx >> 16;
    int r = idx & 65535;
    int n = r >> 10;
    int e = r & 1023;
    const float* W = (w == 0) ? Wk : (w == 1) ? Wq : Wv;
#pragma unroll
    for (int j = 0; j < 4; j++) {
        float v = W[(size_t)(e + j) * H_DIM + n];
        __nv_bfloat16 hi = __float2bfloat16(v);
        __nv_bfloat16 lo = __float2bfloat16(v - __bfloat162float(hi));
        g_wt_hi[idx + j] = hi;
        g_wt_lo[idx + j] = lo;
    }
}

// ================= Kernel 1: HMMA projection (Ootomo bf16x3) ===============
#define A_STR 40
#define B_STR 40

__global__ __launch_bounds__(256) void proj_mma_kernel(const float* __restrict__ x)
{
    __shared__ __nv_bfloat16 sA_hi[64 * A_STR];
    __shared__ __nv_bfloat16 sA_lo[64 * A_STR];
    __shared__ __nv_bfloat16 sB_hi[192 * B_STR];
    __shared__ __nv_bfloat16 sB_lo[192 * B_STR];

    const int tid = threadIdx.x;
    const int wid = tid >> 5;
    const int lane = tid & 31;
    const int m0 = blockIdx.x * 64;
    const int wm = (wid & 3) * 16;
    const int wn = (wid >> 2) * 96;

    float acc[12][4];
#pragma unroll
    for (int nt = 0; nt < 12; nt++)
#pragma unroll
        for (int j = 0; j < 4; j++) acc[nt][j] = 0.0f;

    const int amat = lane >> 3, ar = lane & 7;
    const int a_row = (amat & 1) * 8 + ar;
    const int a_kblk = (amat >> 1) * 8;
    uint32_t ah_base = smem_u32(sA_hi) + ((wm + a_row) * A_STR + a_kblk) * 2;
    uint32_t al_base = smem_u32(sA_lo) + ((wm + a_row) * A_STR + a_kblk) * 2;
    const int b_row = lane & 7;
    const int b_kblk = ((lane >> 3) & 1) * 8;
    uint32_t bh_base = smem_u32(sB_hi) + ((wn + b_row) * B_STR + b_kblk) * 2;
    uint32_t bl_base = smem_u32(sB_lo) + ((wn + b_row) * B_STR + b_kblk) * 2;

    for (int ch = 0; ch < 32; ch++) {
        const int e0 = ch * 32;
        __syncthreads();
#pragma unroll
        for (int it = 0; it < 2; it++) {
            int flat = it * 256 + tid;
            int row = flat >> 3;
            int c4 = flat & 7;
            float4 v = *(const float4*)&x[(size_t)(m0 + row) * E_DIM + e0 + c4 * 4];
            __nv_bfloat16 h0 = __float2bfloat16(v.x);
            __nv_bfloat16 h1 = __float2bfloat16(v.y);
            __nv_bfloat16 h2 = __float2bfloat16(v.z);
            __nv_bfloat16 h3 = __float2bfloat16(v.w);
            __nv_bfloat162 hp0; hp0.x = h0; hp0.y = h1;
            __nv_bfloat162 hp1; hp1.x = h2; hp1.y = h3;
            __nv_bfloat162 lp0;
            lp0.x = __float2bfloat16(v.x - __bfloat162float(h0));
            lp0.y = __float2bfloat16(v.y - __bfloat162float(h1));
            __nv_bfloat162 lp1;
            lp1.x = __float2bfloat16(v.z - __bfloat162float(h2));
            lp1.y = __float2bfloat16(v.w - __bfloat162float(h3));
            int off = row * A_STR + c4 * 4;
            *(__nv_bfloat162*)&sA_hi[off]     = hp0;
            *(__nv_bfloat162*)&sA_hi[off + 2] = hp1;
            *(__nv_bfloat162*)&sA_lo[off]     = lp0;
            *(__nv_bfloat162*)&sA_lo[off + 2] = lp1;
        }
#pragma unroll
        for (int it = 0; it < 3; it++) {
            int flat = it * 256 + tid;
            int n = flat >> 2;
            int u = flat & 3;
            float4 vh = *(const float4*)&g_wt_hi[(size_t)n * 1024 + e0 + u * 8];
            float4 vl = *(const float4*)&g_wt_lo[(size_t)n * 1024 + e0 + u * 8];
            *(float4*)&sB_hi[n * B_STR + u * 8] = vh;
            *(float4*)&sB_lo[n * B_STR + u * 8] = vl;
        }
        __syncthreads();

#pragma unroll
        for (int ks = 0; ks < 2; ks++) {
            const int koff = ks * 16 * 2;
            uint32_t ah0, ah1, ah2, ah3, al0, al1, al2, al3;
            LDSM_X4(ah0, ah1, ah2, ah3, ah_base + koff);
            LDSM_X4(al0, al1, al2, al3, al_base + koff);
#pragma unroll
            for (int nt = 0; nt < 12; nt++) {
                const int noff = nt * 8 * B_STR * 2;
                uint32_t bh0, bh1, bl0, bl1;
                LDSM_X2(bh0, bh1, bh_base + noff + koff);
                LDSM_X2(bl0, bl1, bl_base + noff + koff);
                mma_bf16(acc[nt], ah0, ah1, ah2, ah3, bh0, bh1);
                mma_bf16(acc[nt], ah0, ah1, ah2, ah3, bl0, bl1);
                mma_bf16(acc[nt], al0, al1, al2, al3, bh0, bh1);
            }
        }
    }

    // epilogue -> bf16 hi/lo q/k/v (q pre-scaled by 0.125)
    const int r0 = m0 + wm + (lane >> 2);
#pragma unroll
    for (int nt = 0; nt < 12; nt++) {
        int nglob = wn + nt * 8 + (lane & 3) * 2;
        int wsel = nglob >> 6;
        int col = nglob & 63;
        __nv_bfloat16 *oh, *ol;
        if (wsel == 0)      { oh = g_kh; ol = g_kl; }
        else if (wsel == 1) { oh = g_qh; ol = g_ql; }
        else                { oh = g_vh; ol = g_vl; }
        float sc = (wsel == 1) ? 0.125f : 1.0f;
        float v0 = acc[nt][0] * sc, v1 = acc[nt][1] * sc;
        float v2 = acc[nt][2] * sc, v3 = acc[nt][3] * sc;
        uint32_t h01 = cvt2(v1, v0);
        uint32_t l01 = resid2(h01, v1, v0);
        uint32_t h23 = cvt2(v3, v2);
        uint32_t l23 = resid2(h23, v3, v2);
        *(uint32_t*)&oh[(size_t)r0 * H_DIM + col] = h01;
        *(uint32_t*)&ol[(size_t)r0 * H_DIM + col] = l01;
        *(uint32_t*)&oh[(size_t)(r0 + 8) * H_DIM + col] = h23;
        *(uint32_t*)&ol[(size_t)(r0 + 8) * H_DIM + col] = l23;
    }
}

// ================= Kernel 2: HMMA split-K flash attention (causal) =========
// CTA: 128 q-rows, chunks of <=4 k-tiles (64). 8 warps x 16 rows.
// S = Qh*Kh + Qh*Kl + Ql*Kh; P split hi/lo in regs; O += Ph*Vh + Ph*Vl + Pl*Vh.
#define KSTR 72
#define ATTN_SMEM_BYTES ((2 * QT * KSTR + 4 * 64 * KSTR) * 2)   // 73728 B

__global__ __launch_bounds__(256) void attn_kernel()
{
    extern __shared__ __nv_bfloat16 sb[];
    __nv_bfloat16* sQh = sb;                         // [128][72]
    __nv_bfloat16* sQl = sb + QT * KSTR;
    __nv_bfloat16* sKh = sb + 2 * QT * KSTR;         // [64][72]
    __nv_bfloat16* sKl = sKh + 64 * KSTR;
    __nv_bfloat16* sVh = sKh + 2 * 64 * KSTR;        // V^T: [h][t]
    __nv_bfloat16* sVl = sKh + 3 * 64 * KSTR;

    const int tid = threadIdx.x;
    const int wid = tid >> 5;
    const int lane = tid & 31;
    const int b = blockIdx.y;

    // chunk map: qi in [0,16), nc = ceil((2qi+2)/4)
    int f = blockIdx.x;
    int qi = 0, pre = 0;
    while (pre + ((qi + 2) >> 1) <= f) { pre += (qi + 2) >> 1; qi++; }
    const int c = f - pre;
    const int nc = (qi + 2) >> 1;
    const int ntk = 2 * qi + 2;
    const int base = ntk / nc, rem = ntk % nc;
    const int my = base + (c < rem ? 1 : 0);
    const int start = c * base + (c < rem ? c : rem);
    const int q0 = qi * QT;

    // load Q tile (128x64 bf16 hi/lo)
    {
        const __nv_bfloat16* qh = g_qh + ((size_t)b * T_DIM + q0) * H_DIM;
        const __nv_bfloat16* ql = g_ql + ((size_t)b * T_DIM + q0) * H_DIM;
#pragma unroll
        for (int it = 0; it < 4; it++) {
            int flat = it * 256 + tid;
            int row = flat >> 3;
            int u = flat & 7;
            *(float4*)&sQh[row * KSTR + u * 8] = *(const float4*)&qh[(size_t)row * H_DIM + u * 8];
            *(float4*)&sQl[row * KSTR + u * 8] = *(const float4*)&ql[(size_t)row * H_DIM + u * 8];
        }
    }

    const int wm = wid * 16;
    const int amat = lane >> 3, ar = lane & 7;
    const int a_row = (amat & 1) * 8 + ar;
    const int a_kblk = (amat >> 1) * 8;
    uint32_t qh_base = smem_u32(sQh) + ((wm + a_row) * KSTR + a_kblk) * 2;
    uint32_t ql_base = smem_u32(sQl) + ((wm + a_row) * KSTR + a_kblk) * 2;
    const int b_row = lane & 7;
    const int b_kblk = ((lane >> 3) & 1) * 8;
    uint32_t kh_base = smem_u32(sKh) + (b_row * KSTR + b_kblk) * 2;
    uint32_t kl_base = smem_u32(sKl) + (b_row * KSTR + b_kblk) * 2;
    uint32_t vh_base = smem_u32(sVh) + (b_row * KSTR + b_kblk) * 2;
    uint32_t vl_base = smem_u32(sVl) + (b_row * KSTR + b_kblk) * 2;

    float m0 = -1e30f, m1 = -1e30f, l0 = 0.0f, l1 = 0.0f;
    float o[8][4];
#pragma unroll
    for (int nt = 0; nt < 8; nt++)
#pragma unroll
        for (int j = 0; j < 4; j++) o[nt][j] = 0.0f;

    const int grow0 = q0 + wm + (lane >> 2);
    const int grow1 = grow0 + 8;

    for (int t = 0; t < my; t++) {
        const int ki = start + t;
        const int n0 = ki * 64;
        __syncthreads();
        {
            const __nv_bfloat16* kh = g_kh + ((size_t)b * T_DIM + n0) * H_DIM;
            const __nv_bfloat16* kl = g_kl + ((size_t)b * T_DIM + n0) * H_DIM;
            const __nv_bfloat16* vh = g_vh + ((size_t)b * T_DIM + n0) * H_DIM;
            const __nv_bfloat16* vl = g_vl + ((size_t)b * T_DIM + n0) * H_DIM;
#pragma unroll
            for (int it = 0; it < 2; it++) {
                int flat = it * 256 + tid;
                int row = flat >> 3;      // token within tile
                int u = flat & 7;
                *(float4*)&sKh[row * KSTR + u * 8] = *(const float4*)&kh[(size_t)row * H_DIM + u * 8];
                *(float4*)&sKl[row * KSTR + u * 8] = *(const float4*)&kl[(size_t)row * H_DIM + u * 8];
                // V transposed store: [h][t]
                float4 hv = *(const float4*)&vh[(size_t)row * H_DIM + u * 8];
                float4 lv = *(const float4*)&vl[(size_t)row * H_DIM + u * 8];
                const __nv_bfloat16* hvp = (const __nv_bfloat16*)&hv;
                const __nv_bfloat16* lvp = (const __nv_bfloat16*)&lv;
#pragma unroll
                for (int j = 0; j < 8; j++) {
                    sVh[(u * 8 + j) * KSTR + row] = hvp[j];
                    sVl[(u * 8 + j) * KSTR + row] = lvp[j];
                }
            }
        }
        __syncthreads();

        // ---- S = Q K^T ----
        float s[8][4];
#pragma unroll
        for (int nt = 0; nt < 8; nt++)
#pragma unroll
            for (int j = 0; j < 4; j++) s[nt][j] = 0.0f;

#pragma unroll
        for (int ks = 0; ks < 4; ks++) {
            uint32_t ah0, ah1, ah2, ah3, al0, al1, al2, al3;
            LDSM_X4(ah0, ah1, ah2, ah3, qh_base + ks * 32);
            LDSM_X4(al0, al1, al2, al3, ql_base + ks * 32);
#pragma unroll
            for (int nt = 0; nt < 8; nt++) {
                const int noff = nt * 8 * KSTR * 2 + ks * 32;
                uint32_t bh0, bh1, bl0, bl1;
                LDSM_X2(bh0, bh1, kh_base + noff);
                LDSM_X2(bl0, bl1, kl_base + noff);
                mma_bf16(s[nt], ah0, ah1, ah2, ah3, bh0, bh1);
                mma_bf16(s[nt], ah0, ah1, ah2, ah3, bl0, bl1);
                mma_bf16(s[nt], al0, al1, al2, al3, bh0, bh1);
            }
        }

        // ---- causal mask (only tiles that touch the diagonal) ----
        if (n0 + 63 > q0 + wm) {
#pragma unroll
            for (int nt = 0; nt < 8; nt++) {
                int cb = n0 + nt * 8 + (lane & 3) * 2;
                if (cb > grow0)     s[nt][0] = -1e30f;
                if (cb + 1 > grow0) s[nt][1] = -1e30f;
                if (cb > grow1)     s[nt][2] = -1e30f;
                if (cb + 1 > grow1) s[nt][3] = -1e30f;
            }
        }

        // ---- online softmax (2 rows per thread) ----
        {
            float rm = -1e30f;
#pragma unroll
            for (int nt = 0; nt < 8; nt++) rm = fmaxf(rm, fmaxf(s[nt][0], s[nt][1]));
            rm = fmaxf(rm, __shfl_xor_sync(0xffffffffu, rm, 1));
            rm = fmaxf(rm, __shfl_xor_sync(0xffffffffu, rm, 2));
            float mn = fmaxf(m0, rm);
            float al = __expf(m0 - mn);
            m0 = mn;
            float rs = 0.0f;
#pragma unroll
            for (int nt = 0; nt < 8; nt++) {
                s[nt][0] = __expf(s[nt][0] - mn);
                s[nt][1] = __expf(s[nt][1] - mn);
                rs += s[nt][0] + s[nt][1];
            }
            rs += __shfl_xor_sync(0xffffffffu, rs, 1);
            rs += __shfl_xor_sync(0xffffffffu, rs, 2);
            l0 = l0 * al + rs;
#pragma unroll
            for (int nt = 0; nt < 8; nt++) { o[nt][0] *= al; o[nt][1] *= al; }
        }
        {
            float rm = -1e30f;
#pragma unroll
            for (int nt = 0; nt < 8; nt++) rm = fmaxf(rm, fmaxf(s[nt][2], s[nt][3]));
            rm = fmaxf(rm, __shfl_xor_sync(0xffffffffu, rm, 1));
            rm = fmaxf(rm, __shfl_xor_sync(0xffffffffu, rm, 2));
            float mn = fmaxf(m1, rm);
            float al = __expf(m1 - mn);
            m1 = mn;
            float rs = 0.0f;
#pragma unroll
            for (int nt = 0; nt < 8; nt++) {
                s[nt][2] = __expf(s[nt][2] - mn);
                s[nt][3] = __expf(s[nt][3] - mn);
                rs += s[nt][2] + s[nt][3];
            }
            rs += __shfl_xor_sync(0xffffffffu, rs, 1);
            rs += __shfl_xor_sync(0xffffffffu, rs, 2);
            l1 = l1 * al + rs;
#pragma unroll
            for (int nt = 0; nt < 8; nt++) { o[nt][2] *= al; o[nt][3] *= al; }
        }

        // ---- O += P V (P hi/lo from S accumulators) ----
#pragma unroll
        for (int ks = 0; ks < 4; ks++) {
            uint32_t ph0 = cvt2(s[2 * ks][1],     s[2 * ks][0]);
            uint32_t ph1 = cvt2(s[2 * ks][3],     s[2 * ks][2]);
            uint32_t ph2 = cvt2(s[2 * ks + 1][1], s[2 * ks + 1][0]);
            uint32_t ph3 = cvt2(s[2 * ks + 1][3], s[2 * ks + 1][2]);
            uint32_t pl0 = resid2(ph0, s[2 * ks][1],     s[2 * ks][0]);
            uint32_t pl1 = resid2(ph1, s[2 * ks][3],     s[2 * ks][2]);
            uint32_t pl2 = resid2(ph2, s[2 * ks + 1][1], s[2 * ks + 1][0]);
            uint32_t pl3 = resid2(ph3, s[2 * ks + 1][3], s[2 * ks + 1][2]);
#pragma unroll
            for (int nt = 0; nt < 8; nt++) {
                const int noff = nt * 8 * KSTR * 2 + ks * 32;
                uint32_t vh0, vh1, vl0, vl1;
                LDSM_X2(vh0, vh1, vh_base + noff);
                LDSM_X2(vl0, vl1, vl_base + noff);
                mma_bf16(o[nt], ph0, ph1, ph2, ph3, vh0, vh1);
                mma_bf16(o[nt], ph0, ph1, ph2, ph3, vl0, vl1);
                mma_bf16(o[nt], pl0, pl1, pl2, pl3, vh0, vh1);
            }
        }
    }

    // ---- write partial (unnormalized O, m, l) ----
    const size_t pb = (size_t)(b * NQT2 + qi) * MAXC2 + c;
    float* pO = g_pO + pb * (QT * H_DIM);
    const int r0 = wm + (lane >> 2);
    const int cb = (lane & 3) * 2;
#pragma unroll
    for (int nt = 0; nt < 8; nt++) {
        *(float2*)&pO[(r0)     * H_DIM + nt * 8 + cb] = make_float2(o[nt][0], o[nt][1]);
        *(float2*)&pO[(r0 + 8) * H_DIM + nt * 8 + cb] = make_float2(o[nt][2], o[nt][3]);
    }
    if ((lane & 3) == 0) {
        g_pm[pb * QT + r0] = m0;     g_pl[pb * QT + r0] = l0;
        g_pm[pb * QT + r0 + 8] = m1; g_pl[pb * QT + r0 + 8] = l1;
    }
}

// ================= Kernel 3: combine partials =================
// Grid (NQT2, B), 256 threads: row = tid>>1 (0..127), half = (tid&1)*32 cols.
__global__ __launch_bounds__(256) void combine_kernel(float* __restrict__ out)
{
    const int qi = blockIdx.x;
    const int b = blockIdx.y;
    const int nc = (qi + 2) >> 1;
    const int tid = threadIdx.x;
    const int row = tid >> 1;
    const int cg = (tid & 1) * 32;

    const size_t pb0 = (size_t)(b * NQT2 + qi) * MAXC2;

    float mg = -1e30f;
    for (int c = 0; c < nc; c++)
        mg = fmaxf(mg, g_pm[(pb0 + c) * QT + row]);

    float lg = 0.0f;
    for (int c = 0; c < nc; c++)
        lg += g_pl[(pb0 + c) * QT + row] * __expf(g_pm[(pb0 + c) * QT + row] - mg);
    float inv = 1.0f / lg;

    float4 acc[8];
#pragma unroll
    for (int g = 0; g < 8; g++) acc[g] = make_float4(0.f, 0.f, 0.f, 0.f);

    for (int c = 0; c < nc; c++) {
        float w = __expf(g_pm[(pb0 + c) * QT + row] - mg);
        const float* pO = g_pO + (pb0 + c) * (QT * H_DIM) + row * H_DIM + cg;
#pragma unroll
        for (int g = 0; g < 8; g++) {
            float4 t = *(const float4*)&pO[g * 4];
            acc[g].x += w * t.x; acc[g].y += w * t.y;
            acc[g].z += w * t.z; acc[g].w += w * t.w;
        }
    }

    float* o = out + ((size_t)b * T_DIM + qi * QT + row) * H_DIM + cg;
#pragma unroll
    for (int g = 0; g < 8; g++) {
        float4 r = make_float4(acc[g].x * inv, acc[g].y * inv,
                               acc[g].z * inv, acc[g].w * inv);
        *(float4*)&o[g * 4] = r;
    }
}

extern "C" void kernel_launch(void* const* d_in, const int* in_sizes, int n_in,
                              void* d_out, int out_size)
{
    (void)in_sizes; (void)n_in; (void)out_size;
    const float* x  = (const float*)d_in[0];
    const float* Wk = (const float*)d_in[1];
    const float* Wq = (const float*)d_in[2];
    const float* Wv = (const float*)d_in[3];
    float* out = (float*)d_out;

    static bool attr_set = false;
    if (!attr_set) {
        cudaFuncSetAttribute(attn_kernel,
                             cudaFuncAttributeMaxDynamicSharedMemorySize,
                             ATTN_SMEM_BYTES);
        attr_set = true;
    }

    prep_w_kernel<<<192, 256>>>(Wk, Wq, Wv);
    proj_mma_kernel<<<M_DIM / 64, 256>>>(x);
    attn_kernel<<<dim3(CH2_PER_B, B_DIM), 256, ATTN_SMEM_BYTES>>>();
    combine_kernel<<<dim3(NQT2, B_DIM), 256>>>(out);
}

// round 7
// speedup vs baseline: 3.0681x; 1.0878x over previous
#include <cuda_runtime.h>
#include <cuda_bf16.h>
#include <cstdint>
#include <cstddef>

// Shapes fixed by the dataset.
#define B_DIM 8
#define T_DIM 2048
#define E_DIM 1024
#define H_DIM 64
#define M_DIM (B_DIM * T_DIM)   // 16384
#define NQT2  16                // 128-row q-tiles per batch
#define MAXC2 8
#define CH2_PER_B 72            // sum_{qi=0}^{15} ceil((2qi+2)/4)
#define QT 128

// Device-global scratch (allocation-free). q/k/v stored bf16 hi/lo (Ootomo split).
__device__ __nv_bfloat16 g_qh[M_DIM * H_DIM];
__device__ __nv_bfloat16 g_ql[M_DIM * H_DIM];
__device__ __nv_bfloat16 g_kh[M_DIM * H_DIM];
__device__ __nv_bfloat16 g_kl[M_DIM * H_DIM];
__device__ __nv_bfloat16 g_vh[M_DIM * H_DIM];
__device__ __nv_bfloat16 g_vl[M_DIM * H_DIM];
__device__ float g_pO[(size_t)B_DIM * NQT2 * MAXC2 * QT * H_DIM];
__device__ float g_pm[B_DIM * NQT2 * MAXC2 * QT];
__device__ float g_pl[B_DIM * NQT2 * MAXC2 * QT];
// W transposed + bf16-split: [3][64(n)][1024(e)]
__device__ __nv_bfloat16 g_wt_hi[3 * 64 * 1024];
__device__ __nv_bfloat16 g_wt_lo[3 * 64 * 1024];

extern __shared__ char dynsmem[];

// ---------------- helpers ----------------
__device__ __forceinline__ uint32_t smem_u32(const void* p) {
    uint32_t a;
    asm("{ .reg .u64 t; cvta.to.shared.u64 t, %1; cvt.u32.u64 %0, t; }"
        : "=r"(a) : "l"(p));
    return a;
}
#define LDSM_X4(r0, r1, r2, r3, a)                                             \
    asm volatile("ldmatrix.sync.aligned.m8n8.x4.shared.b16 {%0,%1,%2,%3}, [%4];" \
                 : "=r"(r0), "=r"(r1), "=r"(r2), "=r"(r3) : "r"(a))
#define LDSM_X2(r0, r1, a)                                                     \
    asm volatile("ldmatrix.sync.aligned.m8n8.x2.shared.b16 {%0,%1}, [%2];"     \
                 : "=r"(r0), "=r"(r1) : "r"(a))
#define LDSM_X2_T(r0, r1, a)                                                   \
    asm volatile("ldmatrix.sync.aligned.m8n8.x2.trans.shared.b16 {%0,%1}, [%2];" \
                 : "=r"(r0), "=r"(r1) : "r"(a))
__device__ __forceinline__ void mma_bf16(float d[4], uint32_t a0, uint32_t a1,
                                         uint32_t a2, uint32_t a3,
                                         uint32_t b0, uint32_t b1) {
    asm volatile(
        "mma.sync.aligned.m16n8k16.row.col.f32.bf16.bf16.f32 "
        "{%0,%1,%2,%3}, {%4,%5,%6,%7}, {%8,%9}, {%0,%1,%2,%3};"
        : "+f"(d[0]), "+f"(d[1]), "+f"(d[2]), "+f"(d[3])
        : "r"(a0), "r"(a1), "r"(a2), "r"(a3), "r"(b0), "r"(b1));
}
__device__ __forceinline__ uint32_t cvt2(float hi, float lo) {
    uint32_t r;
    asm("cvt.rn.bf16x2.f32 %0, %1, %2;" : "=r"(r) : "f"(hi), "f"(lo));
    return r;
}
__device__ __forceinline__ uint32_t resid2(uint32_t h, float hi, float lo) {
    float fl = __uint_as_float(h << 16);
    float fh = __uint_as_float(h & 0xFFFF0000u);
    return cvt2(hi - fh, lo - fl);
}

// ================= Kernel 0: W transpose + bf16 split =================
__global__ __launch_bounds__(256) void prep_w_kernel(
    const float* __restrict__ Wk,
    const float* __restrict__ Wq,
    const float* __restrict__ Wv)
{
    int idx = (blockIdx.x * 256 + threadIdx.x) * 4;
    int w = idx >> 16;
    int r = idx & 65535;
    int n = r >> 10;
    int e = r & 1023;
    const float* W = (w == 0) ? Wk : (w == 1) ? Wq : Wv;
#pragma unroll
    for (int j = 0; j < 4; j++) {
        float v = W[(size_t)(e + j) * H_DIM + n];
        __nv_bfloat16 hi = __float2bfloat16(v);
        __nv_bfloat16 lo = __float2bfloat16(v - __bfloat162float(hi));
        g_wt_hi[idx + j] = hi;
        g_wt_lo[idx + j] = lo;
    }
}

// ================= Kernel 1: HMMA projection (Ootomo bf16x3) ===============
// M=128 per CTA (grid 128), 512 threads = 16 warps: (wid&7)->m-tile, (wid>>3)->n-half.
#define A_STR 40
#define B_STR 40
#define PROJ_SMEM_BYTES ((2 * 128 * A_STR + 2 * 192 * B_STR) * 2)   // 51200

__global__ __launch_bounds__(512) void proj_mma_kernel(const float* __restrict__ x)
{
    __nv_bfloat16* ps   = (__nv_bfloat16*)dynsmem;
    __nv_bfloat16* sA_hi = ps;                       // [128][40]
    __nv_bfloat16* sA_lo = ps + 128 * A_STR;
    __nv_bfloat16* sB_hi = ps + 2 * 128 * A_STR;     // [192][40]
    __nv_bfloat16* sB_lo = ps + 2 * 128 * A_STR + 192 * B_STR;

    const int tid = threadIdx.x;
    const int wid = tid >> 5;
    const int lane = tid & 31;
    const int m0 = blockIdx.x * 128;
    const int wm = (wid & 7) * 16;
    const int wn = (wid >> 3) * 96;

    float acc[12][4];
#pragma unroll
    for (int nt = 0; nt < 12; nt++)
#pragma unroll
        for (int j = 0; j < 4; j++) acc[nt][j] = 0.0f;

    const int amat = lane >> 3, ar = lane & 7;
    const int a_row = (amat & 1) * 8 + ar;
    const int a_kblk = (amat >> 1) * 8;
    uint32_t ah_base = smem_u32(sA_hi) + ((wm + a_row) * A_STR + a_kblk) * 2;
    uint32_t al_base = smem_u32(sA_lo) + ((wm + a_row) * A_STR + a_kblk) * 2;
    const int b_row = lane & 7;
    const int b_kblk = ((lane >> 3) & 1) * 8;
    uint32_t bh_base = smem_u32(sB_hi) + ((wn + b_row) * B_STR + b_kblk) * 2;
    uint32_t bl_base = smem_u32(sB_lo) + ((wn + b_row) * B_STR + b_kblk) * 2;

    for (int ch = 0; ch < 32; ch++) {
        const int e0 = ch * 32;
        __syncthreads();
        // A: x[128][32] fp32 -> bf16 hi/lo (1024 float4 over 512 threads)
#pragma unroll
        for (int it = 0; it < 2; it++) {
            int flat = it * 512 + tid;
            int row = flat >> 3;
            int c4 = flat & 7;
            float4 v = *(const float4*)&x[(size_t)(m0 + row) * E_DIM + e0 + c4 * 4];
            __nv_bfloat16 h0 = __float2bfloat16(v.x);
            __nv_bfloat16 h1 = __float2bfloat16(v.y);
            __nv_bfloat16 h2 = __float2bfloat16(v.z);
            __nv_bfloat16 h3 = __float2bfloat16(v.w);
            __nv_bfloat162 hp0; hp0.x = h0; hp0.y = h1;
            __nv_bfloat162 hp1; hp1.x = h2; hp1.y = h3;
            __nv_bfloat162 lp0;
            lp0.x = __float2bfloat16(v.x - __bfloat162float(h0));
            lp0.y = __float2bfloat16(v.y - __bfloat162float(h1));
            __nv_bfloat162 lp1;
            lp1.x = __float2bfloat16(v.z - __bfloat162float(h2));
            lp1.y = __float2bfloat16(v.w - __bfloat162float(h3));
            int off = row * A_STR + c4 * 4;
            *(__nv_bfloat162*)&sA_hi[off]     = hp0;
            *(__nv_bfloat162*)&sA_hi[off + 2] = hp1;
            *(__nv_bfloat162*)&sA_lo[off]     = lp0;
            *(__nv_bfloat162*)&sA_lo[off + 2] = lp1;
        }
        // B: 768 float4-pairs over 512 threads
#pragma unroll
        for (int it = 0; it < 2; it++) {
            int flat = it * 512 + tid;
            if (flat < 768) {
                int n = flat >> 2;
                int u = flat & 3;
                float4 vh = *(const float4*)&g_wt_hi[(size_t)n * 1024 + e0 + u * 8];
                float4 vl = *(const float4*)&g_wt_lo[(size_t)n * 1024 + e0 + u * 8];
                *(float4*)&sB_hi[n * B_STR + u * 8] = vh;
                *(float4*)&sB_lo[n * B_STR + u * 8] = vl;
            }
        }
        __syncthreads();

#pragma unroll
        for (int ks = 0; ks < 2; ks++) {
            const int koff = ks * 32;
            uint32_t ah0, ah1, ah2, ah3, al0, al1, al2, al3;
            LDSM_X4(ah0, ah1, ah2, ah3, ah_base + koff);
            LDSM_X4(al0, al1, al2, al3, al_base + koff);
#pragma unroll
            for (int nt = 0; nt < 12; nt++) {
                const int noff = nt * 8 * B_STR * 2;
                uint32_t bh0, bh1, bl0, bl1;
                LDSM_X2(bh0, bh1, bh_base + noff + koff);
                LDSM_X2(bl0, bl1, bl_base + noff + koff);
                mma_bf16(acc[nt], ah0, ah1, ah2, ah3, bh0, bh1);
                mma_bf16(acc[nt], ah0, ah1, ah2, ah3, bl0, bl1);
                mma_bf16(acc[nt], al0, al1, al2, al3, bh0, bh1);
            }
        }
    }

    // epilogue -> bf16 hi/lo q/k/v (q pre-scaled by 0.125)
    const int r0 = m0 + wm + (lane >> 2);
#pragma unroll
    for (int nt = 0; nt < 12; nt++) {
        int nglob = wn + nt * 8 + (lane & 3) * 2;
        int wsel = nglob >> 6;
        int col = nglob & 63;
        __nv_bfloat16 *oh, *ol;
        if (wsel == 0)      { oh = g_kh; ol = g_kl; }
        else if (wsel == 1) { oh = g_qh; ol = g_ql; }
        else                { oh = g_vh; ol = g_vl; }
        float sc = (wsel == 1) ? 0.125f : 1.0f;
        float v0 = acc[nt][0] * sc, v1 = acc[nt][1] * sc;
        float v2 = acc[nt][2] * sc, v3 = acc[nt][3] * sc;
        uint32_t h01 = cvt2(v1, v0);
        uint32_t l01 = resid2(h01, v1, v0);
        uint32_t h23 = cvt2(v3, v2);
        uint32_t l23 = resid2(h23, v3, v2);
        *(uint32_t*)&oh[(size_t)r0 * H_DIM + col] = h01;
        *(uint32_t*)&ol[(size_t)r0 * H_DIM + col] = l01;
        *(uint32_t*)&oh[(size_t)(r0 + 8) * H_DIM + col] = h23;
        *(uint32_t*)&ol[(size_t)(r0 + 8) * H_DIM + col] = l23;
    }
}

// ================= Kernel 2: HMMA split-K flash attention (causal) =========
// V stored row-major, B-fragments via ldmatrix.trans. Q-hi fragments hoisted.
#define KSTR 72
#define ATTN_SMEM_BYTES ((2 * QT * KSTR + 4 * 64 * KSTR) * 2)   // 73728 B

__global__ __launch_bounds__(256) void attn_kernel()
{
    __nv_bfloat16* sb = (__nv_bfloat16*)dynsmem;
    __nv_bfloat16* sQh = sb;                         // [128][72]
    __nv_bfloat16* sQl = sb + QT * KSTR;
    __nv_bfloat16* sKh = sb + 2 * QT * KSTR;         // [64][72]
    __nv_bfloat16* sKl = sKh + 64 * KSTR;
    __nv_bfloat16* sVh = sKh + 2 * 64 * KSTR;        // row-major [t][h]
    __nv_bfloat16* sVl = sKh + 3 * 64 * KSTR;

    const int tid = threadIdx.x;
    const int wid = tid >> 5;
    const int lane = tid & 31;
    const int b = blockIdx.y;

    int f = blockIdx.x;
    int qi = 0, pre = 0;
    while (pre + ((qi + 2) >> 1) <= f) { pre += (qi + 2) >> 1; qi++; }
    const int c = f - pre;
    const int nc = (qi + 2) >> 1;
    const int ntk = 2 * qi + 2;
    const int base = ntk / nc, rem = ntk % nc;
    const int my = base + (c < rem ? 1 : 0);
    const int start = c * base + (c < rem ? c : rem);
    const int q0 = qi * QT;

    // load Q tile (128x64 bf16 hi/lo)
    {
        const __nv_bfloat16* qh = g_qh + ((size_t)b * T_DIM + q0) * H_DIM;
        const __nv_bfloat16* ql = g_ql + ((size_t)b * T_DIM + q0) * H_DIM;
#pragma unroll
        for (int it = 0; it < 4; it++) {
            int flat = it * 256 + tid;
            int row = flat >> 3;
            int u = flat & 7;
            *(float4*)&sQh[row * KSTR + u * 8] = *(const float4*)&qh[(size_t)row * H_DIM + u * 8];
            *(float4*)&sQl[row * KSTR + u * 8] = *(const float4*)&ql[(size_t)row * H_DIM + u * 8];
        }
    }

    const int wm = wid * 16;
    const int amat = lane >> 3, ar = lane & 7;
    const int a_row = (amat & 1) * 8 + ar;
    const int a_kblk = (amat >> 1) * 8;
    uint32_t qh_base = smem_u32(sQh) + ((wm + a_row) * KSTR + a_kblk) * 2;
    uint32_t ql_base = smem_u32(sQl) + ((wm + a_row) * KSTR + a_kblk) * 2;
    const int b_row = lane & 7;
    const int b_kblk = ((lane >> 3) & 1) * 8;
    uint32_t kh_base = smem_u32(sKh) + (b_row * KSTR + b_kblk) * 2;
    uint32_t kl_base = smem_u32(sKl) + (b_row * KSTR + b_kblk) * 2;
    // V trans-fragment lane base: row = token (lane&15), col selected per (ks,nt)
    uint32_t vh_base = smem_u32(sVh) + (lane & 15) * KSTR * 2;
    uint32_t vl_base = smem_u32(sVl) + (lane & 15) * KSTR * 2;

    __syncthreads();
    // hoist Q-hi fragments (tile-invariant)
    uint32_t qfh[4][4];
#pragma unroll
    for (int ks = 0; ks < 4; ks++)
        LDSM_X4(qfh[ks][0], qfh[ks][1], qfh[ks][2], qfh[ks][3], qh_base + ks * 32);

    float m0 = -1e30f, m1 = -1e30f, l0 = 0.0f, l1 = 0.0f;
    float o[8][4];
#pragma unroll
    for (int nt = 0; nt < 8; nt++)
#pragma unroll
        for (int j = 0; j < 4; j++) o[nt][j] = 0.0f;

    const int grow0 = q0 + wm + (lane >> 2);
    const int grow1 = grow0 + 8;

    for (int t = 0; t < my; t++) {
        const int ki = start + t;
        const int n0 = ki * 64;
        __syncthreads();
        {
            const __nv_bfloat16* kh = g_kh + ((size_t)b * T_DIM + n0) * H_DIM;
            const __nv_bfloat16* kl = g_kl + ((size_t)b * T_DIM + n0) * H_DIM;
            const __nv_bfloat16* vh = g_vh + ((size_t)b * T_DIM + n0) * H_DIM;
            const __nv_bfloat16* vl = g_vl + ((size_t)b * T_DIM + n0) * H_DIM;
#pragma unroll
            for (int it = 0; it < 2; it++) {
                int flat = it * 256 + tid;
                int row = flat >> 3;
                int u = flat & 7;
                *(float4*)&sKh[row * KSTR + u * 8] = *(const float4*)&kh[(size_t)row * H_DIM + u * 8];
                *(float4*)&sKl[row * KSTR + u * 8] = *(const float4*)&kl[(size_t)row * H_DIM + u * 8];
                *(float4*)&sVh[row * KSTR + u * 8] = *(const float4*)&vh[(size_t)row * H_DIM + u * 8];
                *(float4*)&sVl[row * KSTR + u * 8] = *(const float4*)&vl[(size_t)row * H_DIM + u * 8];
            }
        }
        __syncthreads();

        // ---- S = Q K^T ----
        float s[8][4];
#pragma unroll
        for (int nt = 0; nt < 8; nt++)
#pragma unroll
            for (int j = 0; j < 4; j++) s[nt][j] = 0.0f;

#pragma unroll
        for (int ks = 0; ks < 4; ks++) {
            uint32_t al0, al1, al2, al3;
            LDSM_X4(al0, al1, al2, al3, ql_base + ks * 32);
#pragma unroll
            for (int nt = 0; nt < 8; nt++) {
                const int noff = nt * 8 * KSTR * 2 + ks * 32;
                uint32_t bh0, bh1, bl0, bl1;
                LDSM_X2(bh0, bh1, kh_base + noff);
                LDSM_X2(bl0, bl1, kl_base + noff);
                mma_bf16(s[nt], qfh[ks][0], qfh[ks][1], qfh[ks][2], qfh[ks][3], bh0, bh1);
                mma_bf16(s[nt], qfh[ks][0], qfh[ks][1], qfh[ks][2], qfh[ks][3], bl0, bl1);
                mma_bf16(s[nt], al0, al1, al2, al3, bh0, bh1);
            }
        }

        // ---- causal mask ----
        if (n0 + 63 > q0 + wm) {
#pragma unroll
            for (int nt = 0; nt < 8; nt++) {
                int cb = n0 + nt * 8 + (lane & 3) * 2;
                if (cb > grow0)     s[nt][0] = -1e30f;
                if (cb + 1 > grow0) s[nt][1] = -1e30f;
                if (cb > grow1)     s[nt][2] = -1e30f;
                if (cb + 1 > grow1) s[nt][3] = -1e30f;
            }
        }

        // ---- online softmax (2 rows per thread) ----
        {
            float rm = -1e30f;
#pragma unroll
            for (int nt = 0; nt < 8; nt++) rm = fmaxf(rm, fmaxf(s[nt][0], s[nt][1]));
            rm = fmaxf(rm, __shfl_xor_sync(0xffffffffu, rm, 1));
            rm = fmaxf(rm, __shfl_xor_sync(0xffffffffu, rm, 2));
            float mn = fmaxf(m0, rm);
            float al = __expf(m0 - mn);
            m0 = mn;
            float rs = 0.0f;
#pragma unroll
            for (int nt = 0; nt < 8; nt++) {
                s[nt][0] = __expf(s[nt][0] - mn);
                s[nt][1] = __expf(s[nt][1] - mn);
                rs += s[nt][0] + s[nt][1];
            }
            rs += __shfl_xor_sync(0xffffffffu, rs, 1);
            rs += __shfl_xor_sync(0xffffffffu, rs, 2);
            l0 = l0 * al + rs;
#pragma unroll
            for (int nt = 0; nt < 8; nt++) { o[nt][0] *= al; o[nt][1] *= al; }
        }
        {
            float rm = -1e30f;
#pragma unroll
            for (int nt = 0; nt < 8; nt++) rm = fmaxf(rm, fmaxf(s[nt][2], s[nt][3]));
            rm = fmaxf(rm, __shfl_xor_sync(0xffffffffu, rm, 1));
            rm = fmaxf(rm, __shfl_xor_sync(0xffffffffu, rm, 2));
            float mn = fmaxf(m1, rm);
            float al = __expf(m1 - mn);
            m1 = mn;
            float rs = 0.0f;
#pragma unroll
            for (int nt = 0; nt < 8; nt++) {
                s[nt][2] = __expf(s[nt][2] - mn);
                s[nt][3] = __expf(s[nt][3] - mn);
                rs += s[nt][2] + s[nt][3];
            }
            rs += __shfl_xor_sync(0xffffffffu, rs, 1);
            rs += __shfl_xor_sync(0xffffffffu, rs, 2);
            l1 = l1 * al + rs;
#pragma unroll
            for (int nt = 0; nt < 8; nt++) { o[nt][2] *= al; o[nt][3] *= al; }
        }

        // ---- O += P V (V fragments via ldmatrix.trans on row-major V) ----
#pragma unroll
        for (int ks = 0; ks < 4; ks++) {
            uint32_t ph0 = cvt2(s[2 * ks][1],     s[2 * ks][0]);
            uint32_t ph1 = cvt2(s[2 * ks][3],     s[2 * ks][2]);
            uint32_t ph2 = cvt2(s[2 * ks + 1][1], s[2 * ks + 1][0]);
            uint32_t ph3 = cvt2(s[2 * ks + 1][3], s[2 * ks + 1][2]);
            uint32_t pl0 = resid2(ph0, s[2 * ks][1],     s[2 * ks][0]);
            uint32_t pl1 = resid2(ph1, s[2 * ks][3],     s[2 * ks][2]);
            uint32_t pl2 = resid2(ph2, s[2 * ks + 1][1], s[2 * ks + 1][0]);
            uint32_t pl3 = resid2(ph3, s[2 * ks + 1][3], s[2 * ks + 1][2]);
            const int tko = ks * 16 * KSTR * 2;
#pragma unroll
            for (int nt = 0; nt < 8; nt++) {
                const int off = tko + nt * 16;
                uint32_t vh0, vh1, vl0, vl1;
                LDSM_X2_T(vh0, vh1, vh_base + off);
                LDSM_X2_T(vl0, vl1, vl_base + off);
                mma_bf16(o[nt], ph0, ph1, ph2, ph3, vh0, vh1);
                mma_bf16(o[nt], ph0, ph1, ph2, ph3, vl0, vl1);
                mma_bf16(o[nt], pl0, pl1, pl2, pl3, vh0, vh1);
            }
        }
    }

    // ---- write partial (unnormalized O, m, l) ----
    const size_t pb = (size_t)(b * NQT2 + qi) * MAXC2 + c;
    float* pO = g_pO + pb * (QT * H_DIM);
    const int r0 = wm + (lane >> 2);
    const int cb = (lane & 3) * 2;
#pragma unroll
    for (int nt = 0; nt < 8; nt++) {
        *(float2*)&pO[(r0)     * H_DIM + nt * 8 + cb] = make_float2(o[nt][0], o[nt][1]);
        *(float2*)&pO[(r0 + 8) * H_DIM + nt * 8 + cb] = make_float2(o[nt][2], o[nt][3]);
    }
    if ((lane & 3) == 0) {
        g_pm[pb * QT + r0] = m0;     g_pl[pb * QT + r0] = l0;
        g_pm[pb * QT + r0 + 8] = m1; g_pl[pb * QT + r0 + 8] = l1;
    }
}

// ================= Kernel 3: combine partials =================
// Grid (NQT2*4, B): block handles 32 rows; thread = (row, 8 cols).
__global__ __launch_bounds__(256) void combine_kernel(float* __restrict__ out)
{
    const int qi = blockIdx.x >> 2;
    const int quad = blockIdx.x & 3;
    const int b = blockIdx.y;
    const int nc = (qi + 2) >> 1;
    const int tid = threadIdx.x;
    const int row = quad * 32 + (tid >> 3);
    const int cg = (tid & 7) * 8;

    const size_t pb0 = (size_t)(b * NQT2 + qi) * MAXC2;

    float mg = -1e30f;
    for (int c = 0; c < nc; c++)
        mg = fmaxf(mg, g_pm[(pb0 + c) * QT + row]);

    float lg = 0.0f;
    for (int c = 0; c < nc; c++)
        lg += g_pl[(pb0 + c) * QT + row] * __expf(g_pm[(pb0 + c) * QT + row] - mg);
    float inv = 1.0f / lg;

    float4 a0 = make_float4(0.f, 0.f, 0.f, 0.f);
    float4 a1 = make_float4(0.f, 0.f, 0.f, 0.f);

    for (int c = 0; c < nc; c++) {
        float w = __expf(g_pm[(pb0 + c) * QT + row] - mg);
        const float* pO = g_pO + (pb0 + c) * (QT * H_DIM) + row * H_DIM + cg;
        float4 t0 = *(const float4*)&pO[0];
        float4 t1 = *(const float4*)&pO[4];
        a0.x += w * t0.x; a0.y += w * t0.y; a0.z += w * t0.z; a0.w += w * t0.w;
        a1.x += w * t1.x; a1.y += w * t1.y; a1.z += w * t1.z; a1.w += w * t1.w;
    }

    float* o = out + ((size_t)b * T_DIM + qi * QT + row) * H_DIM + cg;
    *(float4*)&o[0] = make_float4(a0.x * inv, a0.y * inv, a0.z * inv, a0.w * inv);
    *(float4*)&o[4] = make_float4(a1.x * inv, a1.y * inv, a1.z * inv, a1.w * inv);
}

extern "C" void kernel_launch(void* const* d_in, const int* in_sizes, int n_in,
                              void* d_out, int out_size)
{
    (void)in_sizes; (void)n_in; (void)out_size;
    const float* x  = (const float*)d_in[0];
    const float* Wk = (const float*)d_in[1];
    const float* Wq = (const float*)d_in[2];
    const float* Wv = (const float*)d_in[3];
    float* out = (float*)d_out;

    static bool attr_set = false;
    if (!attr_set) {
        cudaFuncSetAttribute(attn_kernel,
                             cudaFuncAttributeMaxDynamicSharedMemorySize,
                             ATTN_SMEM_BYTES);
        cudaFuncSetAttribute(proj_mma_kernel,
                             cudaFuncAttributeMaxDynamicSharedMemorySize,
                             PROJ_SMEM_BYTES);
        attr_set = true;
    }

    prep_w_kernel<<<192, 256>>>(Wk, Wq, Wv);
    proj_mma_kernel<<<M_DIM / 128, 512, PROJ_SMEM_BYTES>>>(x);
    attn_kernel<<<dim3(CH2_PER_B, B_DIM), 256, ATTN_SMEM_BYTES>>>();
    combine_kernel<<<dim3(NQT2 * 4, B_DIM), 256>>>(out);
}

// round 8
// speedup vs baseline: 3.3478x; 1.0911x over previous
#include <cuda_runtime.h>
#include <cuda_bf16.h>
#include <cstdint>
#include <cstddef>

// Shapes fixed by the dataset.
#define B_DIM 8
#define T_DIM 2048
#define E_DIM 1024
#define H_DIM 64
#define M_DIM (B_DIM * T_DIM)   // 16384
#define NQT2  16                // 128-row q-tiles per batch
#define MAXC2 8
#define CH2_PER_B 72            // sum_{qi=0}^{15} ceil((2qi+2)/4)
#define QT 128
#define KSTR 72                 // smem row stride (144B: cp.async-aligned + conflict-free)

// Device-global scratch (allocation-free). q/k/v stored bf16 hi/lo (Ootomo split).
__device__ __nv_bfloat16 g_qh[M_DIM * H_DIM];
__device__ __nv_bfloat16 g_ql[M_DIM * H_DIM];
__device__ __nv_bfloat16 g_kh[M_DIM * H_DIM];
__device__ __nv_bfloat16 g_kl[M_DIM * H_DIM];
__device__ __nv_bfloat16 g_vh[M_DIM * H_DIM];
__device__ __nv_bfloat16 g_vl[M_DIM * H_DIM];
__device__ float g_pO[(size_t)B_DIM * NQT2 * MAXC2 * QT * H_DIM];
__device__ float g_pm[B_DIM * NQT2 * MAXC2 * QT];
__device__ float g_pl[B_DIM * NQT2 * MAXC2 * QT];
// W transposed + bf16-split: [3][64(n)][1024(e)]
__device__ __nv_bfloat16 g_wt_hi[3 * 64 * 1024];
__device__ __nv_bfloat16 g_wt_lo[3 * 64 * 1024];

extern __shared__ char dynsmem[];

// ---------------- helpers ----------------
__device__ __forceinline__ uint32_t smem_u32(const void* p) {
    uint32_t a;
    asm("{ .reg .u64 t; cvta.to.shared.u64 t, %1; cvt.u32.u64 %0, t; }"
        : "=r"(a) : "l"(p));
    return a;
}
#define LDSM_X4(r0, r1, r2, r3, a)                                             \
    asm volatile("ldmatrix.sync.aligned.m8n8.x4.shared.b16 {%0,%1,%2,%3}, [%4];" \
                 : "=r"(r0), "=r"(r1), "=r"(r2), "=r"(r3) : "r"(a))
#define LDSM_X2(r0, r1, a)                                                     \
    asm volatile("ldmatrix.sync.aligned.m8n8.x2.shared.b16 {%0,%1}, [%2];"     \
                 : "=r"(r0), "=r"(r1) : "r"(a))
#define LDSM_X2_T(r0, r1, a)                                                   \
    asm volatile("ldmatrix.sync.aligned.m8n8.x2.trans.shared.b16 {%0,%1}, [%2];" \
                 : "=r"(r0), "=r"(r1) : "r"(a))
__device__ __forceinline__ void mma_bf16(float d[4], uint32_t a0, uint32_t a1,
                                         uint32_t a2, uint32_t a3,
                                         uint32_t b0, uint32_t b1) {
    asm volatile(
        "mma.sync.aligned.m16n8k16.row.col.f32.bf16.bf16.f32 "
        "{%0,%1,%2,%3}, {%4,%5,%6,%7}, {%8,%9}, {%0,%1,%2,%3};"
        : "+f"(d[0]), "+f"(d[1]), "+f"(d[2]), "+f"(d[3])
        : "r"(a0), "r"(a1), "r"(a2), "r"(a3), "r"(b0), "r"(b1));
}
__device__ __forceinline__ uint32_t cvt2(float hi, float lo) {
    uint32_t r;
    asm("cvt.rn.bf16x2.f32 %0, %1, %2;" : "=r"(r) : "f"(hi), "f"(lo));
    return r;
}
__device__ __forceinline__ uint32_t resid2(uint32_t h, float hi, float lo) {
    float fl = __uint_as_float(h << 16);
    float fh = __uint_as_float(h & 0xFFFF0000u);
    return cvt2(hi - fh, lo - fl);
}
__device__ __forceinline__ void cp16(uint32_t dst, const void* src) {
    asm volatile("cp.async.cg.shared.global [%0], [%1], 16;"
                 :: "r"(dst), "l"(__cvta_generic_to_global(src)));
}
#define CP_COMMIT() asm volatile("cp.async.commit_group;" ::: "memory")
#define CP_WAIT(N)  asm volatile("cp.async.wait_group %0;" :: "n"(N) : "memory")

// ================= Kernel 0: W transpose + bf16 split =================
__global__ __launch_bounds__(256) void prep_w_kernel(
    const float* __restrict__ Wk,
    const float* __restrict__ Wq,
    const float* __restrict__ Wv)
{
    int idx = (blockIdx.x * 256 + threadIdx.x) * 4;
    int w = idx >> 16;
    int r = idx & 65535;
    int n = r >> 10;
    int e = r & 1023;
    const float* W = (w == 0) ? Wk : (w == 1) ? Wq : Wv;
#pragma unroll
    for (int j = 0; j < 4; j++) {
        float v = W[(size_t)(e + j) * H_DIM + n];
        __nv_bfloat16 hi = __float2bfloat16(v);
        __nv_bfloat16 lo = __float2bfloat16(v - __bfloat162float(hi));
        g_wt_hi[idx + j] = hi;
        g_wt_lo[idx + j] = lo;
    }
}

// ================= Kernel 1: HMMA projection, cp.async pipelined ===========
// M=128/CTA (grid 128), 512 threads = 16 warps: (wid&7)->m16, (wid>>3)->n-half.
// A (x) loaded straight into mma fragments from global (fp32->bf16 hi/lo in regs),
// next chunk's raw floats prefetched during current compute.
// B (W hi/lo) double-buffered in smem via cp.async.
#define PROJ_STAGE_ELEMS (2 * 192 * KSTR)             // hi+lo per stage
#define PROJ_SMEM_BYTES  (2 * PROJ_STAGE_ELEMS * 2)   // 110592 B

__global__ __launch_bounds__(512, 1) void proj_mma_kernel(const float* __restrict__ x)
{
    __nv_bfloat16* sB = (__nv_bfloat16*)dynsmem;      // [stage][hi/lo][192][KSTR]
    const uint32_t b_u32 = smem_u32(sB);

    const int tid = threadIdx.x;
    const int wid = tid >> 5;
    const int lane = tid & 31;
    const int m0 = blockIdx.x * 128;
    const int wm = (wid & 7) * 16;
    const int wn = (wid >> 3) * 96;

    float acc[12][4];
#pragma unroll
    for (int nt = 0; nt < 12; nt++)
#pragma unroll
        for (int j = 0; j < 4; j++) acc[nt][j] = 0.0f;

    // B fragment lane offset (bytes)
    const int b_off = (((lane & 7)) * KSTR + ((lane >> 3) & 1) * 8) * 2;
    const int bn_off = wn * KSTR * 2;

    // A rows for this thread
    const int arow = m0 + wm + (lane >> 2);
    const float* xp0 = x + (size_t)arow * E_DIM + (lane & 3) * 2;
    const float* xp1 = xp0 + 8 * E_DIM;

    // ---- B prefetch for a chunk into a stage ----
    auto prefetchB = [&](int ch, int st) {
        const int e0 = ch * 32;
        const uint32_t dst0 = b_u32 + st * (PROJ_STAGE_ELEMS * 2);
#pragma unroll
        for (int it = 0; it < 3; it++) {
            int flat = it * 512 + tid;           // 0..1535
            int half = flat >= 768;
            int f = flat - half * 768;
            int n = f >> 2;
            int u = f & 3;
            const __nv_bfloat16* src = (half ? g_wt_lo : g_wt_hi) +
                                       (size_t)n * 1024 + e0 + u * 8;
            cp16(dst0 + (half * 192 * KSTR + n * KSTR + u * 8) * 2, src);
        }
    };
    // ---- A raw loads for a chunk (8 float2) ----
    auto loadA = [&](int ch, float2 r[2][4]) {
        const int e0 = ch * 32;
#pragma unroll
        for (int ks = 0; ks < 2; ks++) {
            int c = e0 + ks * 16;
            r[ks][0] = *(const float2*)&xp0[c];
            r[ks][1] = *(const float2*)&xp1[c];
            r[ks][2] = *(const float2*)&xp0[c + 8];
            r[ks][3] = *(const float2*)&xp1[c + 8];
        }
    };

    float2 curA[2][4], nextA[2][4];
    prefetchB(0, 0);
    CP_COMMIT();
    loadA(0, curA);

    for (int ch = 0; ch < 32; ch++) {
        const int st = ch & 1;
        if (ch + 1 < 32) loadA(ch + 1, nextA);
        __syncthreads();                       // all warps done with stage st^1
        if (ch + 1 < 32) {
            prefetchB(ch + 1, st ^ 1);
            CP_COMMIT();
            CP_WAIT(1);                        // stage st ready
        } else {
            CP_WAIT(0);
        }
        __syncthreads();                       // cp.async data visible to all

        const uint32_t bh0a = b_u32 + st * (PROJ_STAGE_ELEMS * 2) + bn_off + b_off;
        const uint32_t bl0a = bh0a + 192 * KSTR * 2;
#pragma unroll
        for (int ks = 0; ks < 2; ks++) {
            uint32_t ah[4], al[4];
#pragma unroll
            for (int i = 0; i < 4; i++) {
                ah[i] = cvt2(curA[ks][i].y, curA[ks][i].x);
                al[i] = resid2(ah[i], curA[ks][i].y, curA[ks][i].x);
            }
#pragma unroll
            for (int nt = 0; nt < 12; nt++) {
                const int off = nt * 8 * KSTR * 2 + ks * 32;
                uint32_t bh0, bh1, bl0, bl1;
                LDSM_X2(bh0, bh1, bh0a + off);
                LDSM_X2(bl0, bl1, bl0a + off);
                mma_bf16(acc[nt], ah[0], ah[1], ah[2], ah[3], bh0, bh1);
                mma_bf16(acc[nt], ah[0], ah[1], ah[2], ah[3], bl0, bl1);
                mma_bf16(acc[nt], al[0], al[1], al[2], al[3], bh0, bh1);
            }
        }
#pragma unroll
        for (int ks = 0; ks < 2; ks++)
#pragma unroll
            for (int i = 0; i < 4; i++) curA[ks][i] = nextA[ks][i];
    }

    // epilogue -> bf16 hi/lo q/k/v (q pre-scaled by 0.125)
    const int r0 = m0 + wm + (lane >> 2);
#pragma unroll
    for (int nt = 0; nt < 12; nt++) {
        int nglob = wn + nt * 8 + (lane & 3) * 2;
        int wsel = nglob >> 6;
        int col = nglob & 63;
        __nv_bfloat16 *oh, *ol;
        if (wsel == 0)      { oh = g_kh; ol = g_kl; }
        else if (wsel == 1) { oh = g_qh; ol = g_ql; }
        else                { oh = g_vh; ol = g_vl; }
        float sc = (wsel == 1) ? 0.125f : 1.0f;
        float v0 = acc[nt][0] * sc, v1 = acc[nt][1] * sc;
        float v2 = acc[nt][2] * sc, v3 = acc[nt][3] * sc;
        uint32_t h01 = cvt2(v1, v0);
        uint32_t l01 = resid2(h01, v1, v0);
        uint32_t h23 = cvt2(v3, v2);
        uint32_t l23 = resid2(h23, v3, v2);
        *(uint32_t*)&oh[(size_t)r0 * H_DIM + col] = h01;
        *(uint32_t*)&ol[(size_t)r0 * H_DIM + col] = l01;
        *(uint32_t*)&oh[(size_t)(r0 + 8) * H_DIM + col] = h23;
        *(uint32_t*)&ol[(size_t)(r0 + 8) * H_DIM + col] = l23;
    }
}

// ================= Kernel 2: HMMA split-K flash attention, pipelined =======
// K/V hi/lo double-buffered via cp.async. V row-major + ldmatrix.trans.
#define AT_ARR   (64 * KSTR)                      // elements per K/V array
#define AT_STAGE (4 * AT_ARR)                     // elements per stage
#define ATTN_SMEM_BYTES ((2 * QT * KSTR + 2 * AT_STAGE) * 2)   // 110592 B

__global__ __launch_bounds__(256, 2) void attn_kernel()
{
    __nv_bfloat16* sb = (__nv_bfloat16*)dynsmem;
    __nv_bfloat16* sQh = sb;                         // [128][KSTR]
    __nv_bfloat16* sQl = sb + QT * KSTR;
    __nv_bfloat16* kv0 = sb + 2 * QT * KSTR;         // [stage][kh|kl|vh|vl][64][KSTR]
    const uint32_t kv_u32 = smem_u32(kv0);

    const int tid = threadIdx.x;
    const int wid = tid >> 5;
    const int lane = tid & 31;
    const int b = blockIdx.y;

    int f = blockIdx.x;
    int qi = 0, pre = 0;
    while (pre + ((qi + 2) >> 1) <= f) { pre += (qi + 2) >> 1; qi++; }
    const int c = f - pre;
    const int nc = (qi + 2) >> 1;
    const int ntk = 2 * qi + 2;
    const int base = ntk / nc, rem = ntk % nc;
    const int my = base + (c < rem ? 1 : 0);
    const int start = c * base + (c < rem ? c : rem);
    const int q0 = qi * QT;

    // ---- K/V prefetch for a tile into a stage ----
    auto prefetchKV = [&](int ki, int st) {
        const int n0 = ki * 64;
        const uint32_t dst0 = kv_u32 + st * (AT_STAGE * 2);
        const __nv_bfloat16* srcs[4] = {
            g_kh + ((size_t)b * T_DIM + n0) * H_DIM,
            g_kl + ((size_t)b * T_DIM + n0) * H_DIM,
            g_vh + ((size_t)b * T_DIM + n0) * H_DIM,
            g_vl + ((size_t)b * T_DIM + n0) * H_DIM };
#pragma unroll
        for (int it = 0; it < 8; it++) {
            int flat = it * 256 + tid;           // 0..2047
            int arr = flat >> 9;
            int fr = flat & 511;
            int row = fr >> 3;
            int u = fr & 7;
            cp16(dst0 + (arr * AT_ARR + row * KSTR + u * 8) * 2,
                 srcs[arr] + (size_t)row * H_DIM + u * 8);
        }
    };

    prefetchKV(start, 0);
    CP_COMMIT();

    // load Q tile (regular; overlaps with KV prefetch)
    {
        const __nv_bfloat16* qh = g_qh + ((size_t)b * T_DIM + q0) * H_DIM;
        const __nv_bfloat16* ql = g_ql + ((size_t)b * T_DIM + q0) * H_DIM;
#pragma unroll
        for (int it = 0; it < 4; it++) {
            int flat = it * 256 + tid;
            int row = flat >> 3;
            int u = flat & 7;
            *(float4*)&sQh[row * KSTR + u * 8] = *(const float4*)&qh[(size_t)row * H_DIM + u * 8];
            *(float4*)&sQl[row * KSTR + u * 8] = *(const float4*)&ql[(size_t)row * H_DIM + u * 8];
        }
    }

    const int wm = wid * 16;
    const int amat = lane >> 3, ar = lane & 7;
    const int a_row = (amat & 1) * 8 + ar;
    const int a_kblk = (amat >> 1) * 8;
    uint32_t qh_base = smem_u32(sQh) + ((wm + a_row) * KSTR + a_kblk) * 2;
    uint32_t ql_base = smem_u32(sQl) + ((wm + a_row) * KSTR + a_kblk) * 2;
    const int k_off = ((lane & 7) * KSTR + ((lane >> 3) & 1) * 8) * 2;
    const int v_off = (lane & 15) * KSTR * 2;

    __syncthreads();
    // hoist Q-hi fragments (tile-invariant)
    uint32_t qfh[4][4];
#pragma unroll
    for (int ks = 0; ks < 4; ks++)
        LDSM_X4(qfh[ks][0], qfh[ks][1], qfh[ks][2], qfh[ks][3], qh_base + ks * 32);

    float m0 = -1e30f, m1 = -1e30f, l0 = 0.0f, l1 = 0.0f;
    float o[8][4];
#pragma unroll
    for (int nt = 0; nt < 8; nt++)
#pragma unroll
        for (int j = 0; j < 4; j++) o[nt][j] = 0.0f;

    const int grow0 = q0 + wm + (lane >> 2);
    const int grow1 = grow0 + 8;

    for (int t = 0; t < my; t++) {
        const int st = t & 1;
        const int n0 = (start + t) * 64;
        __syncthreads();                 // all warps done with stage st^1
        if (t + 1 < my) {
            prefetchKV(start + t + 1, st ^ 1);
            CP_COMMIT();
            CP_WAIT(1);
        } else {
            CP_WAIT(0);
        }
        __syncthreads();                 // stage st visible

        const uint32_t khb = kv_u32 + st * (AT_STAGE * 2) + k_off;
        const uint32_t klb = khb + AT_ARR * 2;
        const uint32_t vhb = kv_u32 + st * (AT_STAGE * 2) + 2 * AT_ARR * 2 + v_off;
        const uint32_t vlb = vhb + AT_ARR * 2;

        // ---- S = Q K^T ----
        float s[8][4];
#pragma unroll
        for (int nt = 0; nt < 8; nt++)
#pragma unroll
            for (int j = 0; j < 4; j++) s[nt][j] = 0.0f;

#pragma unroll
        for (int ks = 0; ks < 4; ks++) {
            uint32_t al0, al1, al2, al3;
            LDSM_X4(al0, al1, al2, al3, ql_base + ks * 32);
#pragma unroll
            for (int nt = 0; nt < 8; nt++) {
                const int noff = nt * 8 * KSTR * 2 + ks * 32;
                uint32_t bh0, bh1, bl0, bl1;
                LDSM_X2(bh0, bh1, khb + noff);
                LDSM_X2(bl0, bl1, klb + noff);
                mma_bf16(s[nt], qfh[ks][0], qfh[ks][1], qfh[ks][2], qfh[ks][3], bh0, bh1);
                mma_bf16(s[nt], qfh[ks][0], qfh[ks][1], qfh[ks][2], qfh[ks][3], bl0, bl1);
                mma_bf16(s[nt], al0, al1, al2, al3, bh0, bh1);
            }
        }

        // ---- causal mask ----
        if (n0 + 63 > q0 + wm) {
#pragma unroll
            for (int nt = 0; nt < 8; nt++) {
                int cb = n0 + nt * 8 + (lane & 3) * 2;
                if (cb > grow0)     s[nt][0] = -1e30f;
                if (cb + 1 > grow0) s[nt][1] = -1e30f;
                if (cb > grow1)     s[nt][2] = -1e30f;
                if (cb + 1 > grow1) s[nt][3] = -1e30f;
            }
        }

        // ---- online softmax (2 rows per thread) ----
        {
            float rm = -1e30f;
#pragma unroll
            for (int nt = 0; nt < 8; nt++) rm = fmaxf(rm, fmaxf(s[nt][0], s[nt][1]));
            rm = fmaxf(rm, __shfl_xor_sync(0xffffffffu, rm, 1));
            rm = fmaxf(rm, __shfl_xor_sync(0xffffffffu, rm, 2));
            float mn = fmaxf(m0, rm);
            float al = __expf(m0 - mn);
            m0 = mn;
            float rs = 0.0f;
#pragma unroll
            for (int nt = 0; nt < 8; nt++) {
                s[nt][0] = __expf(s[nt][0] - mn);
                s[nt][1] = __expf(s[nt][1] - mn);
                rs += s[nt][0] + s[nt][1];
            }
            rs += __shfl_xor_sync(0xffffffffu, rs, 1);
            rs += __shfl_xor_sync(0xffffffffu, rs, 2);
            l0 = l0 * al + rs;
#pragma unroll
            for (int nt = 0; nt < 8; nt++) { o[nt][0] *= al; o[nt][1] *= al; }
        }
        {
            float rm = -1e30f;
#pragma unroll
            for (int nt = 0; nt < 8; nt++) rm = fmaxf(rm, fmaxf(s[nt][2], s[nt][3]));
            rm = fmaxf(rm, __shfl_xor_sync(0xffffffffu, rm, 1));
            rm = fmaxf(rm, __shfl_xor_sync(0xffffffffu, rm, 2));
            float mn = fmaxf(m1, rm);
            float al = __expf(m1 - mn);
            m1 = mn;
            float rs = 0.0f;
#pragma unroll
            for (int nt = 0; nt < 8; nt++) {
                s[nt][2] = __expf(s[nt][2] - mn);
                s[nt][3] = __expf(s[nt][3] - mn);
                rs += s[nt][2] + s[nt][3];
            }
            rs += __shfl_xor_sync(0xffffffffu, rs, 1);
            rs += __shfl_xor_sync(0xffffffffu, rs, 2);
            l1 = l1 * al + rs;
#pragma unroll
            for (int nt = 0; nt < 8; nt++) { o[nt][2] *= al; o[nt][3] *= al; }
        }

        // ---- O += P V ----
#pragma unroll
        for (int ks = 0; ks < 4; ks++) {
            uint32_t ph0 = cvt2(s[2 * ks][1],     s[2 * ks][0]);
            uint32_t ph1 = cvt2(s[2 * ks][3],     s[2 * ks][2]);
            uint32_t ph2 = cvt2(s[2 * ks + 1][1], s[2 * ks + 1][0]);
            uint32_t ph3 = cvt2(s[2 * ks + 1][3], s[2 * ks + 1][2]);
            uint32_t pl0 = resid2(ph0, s[2 * ks][1],     s[2 * ks][0]);
            uint32_t pl1 = resid2(ph1, s[2 * ks][3],     s[2 * ks][2]);
            uint32_t pl2 = resid2(ph2, s[2 * ks + 1][1], s[2 * ks + 1][0]);
            uint32_t pl3 = resid2(ph3, s[2 * ks + 1][3], s[2 * ks + 1][2]);
            const int tko = ks * 16 * KSTR * 2;
#pragma unroll
            for (int nt = 0; nt < 8; nt++) {
                const int off = tko + nt * 16;
                uint32_t vh0, vh1, vl0, vl1;
                LDSM_X2_T(vh0, vh1, vhb + off);
                LDSM_X2_T(vl0, vl1, vlb + off);
                mma_bf16(o[nt], ph0, ph1, ph2, ph3, vh0, vh1);
                mma_bf16(o[nt], ph0, ph1, ph2, ph3, vl0, vl1);
                mma_bf16(o[nt], pl0, pl1, pl2, pl3, vh0, vh1);
            }
        }
    }

    // ---- write partial (unnormalized O, m, l) ----
    const size_t pb = (size_t)(b * NQT2 + qi) * MAXC2 + c;
    float* pO = g_pO + pb * (QT * H_DIM);
    const int r0 = wm + (lane >> 2);
    const int cb = (lane & 3) * 2;
#pragma unroll
    for (int nt = 0; nt < 8; nt++) {
        *(float2*)&pO[(r0)     * H_DIM + nt * 8 + cb] = make_float2(o[nt][0], o[nt][1]);
        *(float2*)&pO[(r0 + 8) * H_DIM + nt * 8 + cb] = make_float2(o[nt][2], o[nt][3]);
    }
    if ((lane & 3) == 0) {
        g_pm[pb * QT + r0] = m0;     g_pl[pb * QT + r0] = l0;
        g_pm[pb * QT + r0 + 8] = m1; g_pl[pb * QT + r0 + 8] = l1;
    }
}

// ================= Kernel 3: combine partials =================
__global__ __launch_bounds__(256) void combine_kernel(float* __restrict__ out)
{
    const int qi = blockIdx.x >> 2;
    const int quad = blockIdx.x & 3;
    const int b = blockIdx.y;
    const int nc = (qi + 2) >> 1;
    const int tid = threadIdx.x;
    const int row = quad * 32 + (tid >> 3);
    const int cg = (tid & 7) * 8;

    const size_t pb0 = (size_t)(b * NQT2 + qi) * MAXC2;

    float mg = -1e30f;
    for (int c = 0; c < nc; c++)
        mg = fmaxf(mg, g_pm[(pb0 + c) * QT + row]);

    float lg = 0.0f;
    for (int c = 0; c < nc; c++)
        lg += g_pl[(pb0 + c) * QT + row] * __expf(g_pm[(pb0 + c) * QT + row] - mg);
    float inv = 1.0f / lg;

    float4 a0 = make_float4(0.f, 0.f, 0.f, 0.f);
    float4 a1 = make_float4(0.f, 0.f, 0.f, 0.f);

    for (int c = 0; c < nc; c++) {
        float w = __expf(g_pm[(pb0 + c) * QT + row] - mg);
        const float* pO = g_pO + (pb0 + c) * (QT * H_DIM) + row * H_DIM + cg;
        float4 t0 = *(const float4*)&pO[0];
        float4 t1 = *(const float4*)&pO[4];
        a0.x += w * t0.x; a0.y += w * t0.y; a0.z += w * t0.z; a0.w += w * t0.w;
        a1.x += w * t1.x; a1.y += w * t1.y; a1.z += w * t1.z; a1.w += w * t1.w;
    }

    float* o = out + ((size_t)b * T_DIM + qi * QT + row) * H_DIM + cg;
    *(float4*)&o[0] = make_float4(a0.x * inv, a0.y * inv, a0.z * inv, a0.w * inv);
    *(float4*)&o[4] = make_float4(a1.x * inv, a1.y * inv, a1.z * inv, a1.w * inv);
}

extern "C" void kernel_launch(void* const* d_in, const int* in_sizes, int n_in,
                              void* d_out, int out_size)
{
    (void)in_sizes; (void)n_in; (void)out_size;
    const float* x  = (const float*)d_in[0];
    const float* Wk = (const float*)d_in[1];
    const float* Wq = (const float*)d_in[2];
    const float* Wv = (const float*)d_in[3];
    float* out = (float*)d_out;

    static bool attr_set = false;
    if (!attr_set) {
        cudaFuncSetAttribute(attn_kernel,
                             cudaFuncAttributeMaxDynamicSharedMemorySize,
                             ATTN_SMEM_BYTES);
        cudaFuncSetAttribute(proj_mma_kernel,
                             cudaFuncAttributeMaxDynamicSharedMemorySize,
                             PROJ_SMEM_BYTES);
        attr_set = true;
    }

    prep_w_kernel<<<192, 256>>>(Wk, Wq, Wv);
    proj_mma_kernel<<<M_DIM / 128, 512, PROJ_SMEM_BYTES>>>(x);
    attn_kernel<<<dim3(CH2_PER_B, B_DIM), 256, ATTN_SMEM_BYTES>>>();
    combine_kernel<<<dim3(NQT2 * 4, B_DIM), 256>>>(out);
}

// round 9
// speedup vs baseline: 3.4400x; 1.0275x over previous
#include <cuda_runtime.h>
#include <cuda_bf16.h>
#include <cstdint>
#include <cstddef>

// Shapes fixed by the dataset.
#define B_DIM 8
#define T_DIM 2048
#define E_DIM 1024
#define H_DIM 64
#define M_DIM (B_DIM * T_DIM)   // 16384
#define NQT2  16                // 128-row q-tiles per batch
#define MAXC2 8
#define CH2_PER_B 72            // sum_{qi=0}^{15} ceil((2qi+2)/4)
#define QT 128
#define KSTR 72                 // smem row stride (144B: cp.async-aligned + conflict-free)

// Device-global scratch (allocation-free). q/k/v stored bf16 hi/lo (Ootomo split).
__device__ __nv_bfloat16 g_qh[M_DIM * H_DIM];
__device__ __nv_bfloat16 g_ql[M_DIM * H_DIM];
__device__ __nv_bfloat16 g_kh[M_DIM * H_DIM];
__device__ __nv_bfloat16 g_kl[M_DIM * H_DIM];
__device__ __nv_bfloat16 g_vh[M_DIM * H_DIM];
__device__ __nv_bfloat16 g_vl[M_DIM * H_DIM];
__device__ float g_pO[(size_t)B_DIM * NQT2 * MAXC2 * QT * H_DIM];
__device__ float g_pm[B_DIM * NQT2 * MAXC2 * QT];
__device__ float g_pl[B_DIM * NQT2 * MAXC2 * QT];
// W transposed + bf16-split: [3][64(n)][1024(e)]
__device__ __nv_bfloat16 g_wt_hi[3 * 64 * 1024];
__device__ __nv_bfloat16 g_wt_lo[3 * 64 * 1024];

extern __shared__ char dynsmem[];

// ---------------- helpers ----------------
__device__ __forceinline__ uint32_t smem_u32(const void* p) {
    uint32_t a;
    asm("{ .reg .u64 t; cvta.to.shared.u64 t, %1; cvt.u32.u64 %0, t; }"
        : "=r"(a) : "l"(p));
    return a;
}
#define LDSM_X4(r0, r1, r2, r3, a)                                             \
    asm volatile("ldmatrix.sync.aligned.m8n8.x4.shared.b16 {%0,%1,%2,%3}, [%4];" \
                 : "=r"(r0), "=r"(r1), "=r"(r2), "=r"(r3) : "r"(a))
#define LDSM_X4_T(r0, r1, r2, r3, a)                                           \
    asm volatile("ldmatrix.sync.aligned.m8n8.x4.trans.shared.b16 {%0,%1,%2,%3}, [%4];" \
                 : "=r"(r0), "=r"(r1), "=r"(r2), "=r"(r3) : "r"(a))
__device__ __forceinline__ void mma_bf16(float d[4], uint32_t a0, uint32_t a1,
                                         uint32_t a2, uint32_t a3,
                                         uint32_t b0, uint32_t b1) {
    asm volatile(
        "mma.sync.aligned.m16n8k16.row.col.f32.bf16.bf16.f32 "
        "{%0,%1,%2,%3}, {%4,%5,%6,%7}, {%8,%9}, {%0,%1,%2,%3};"
        : "+f"(d[0]), "+f"(d[1]), "+f"(d[2]), "+f"(d[3])
        : "r"(a0), "r"(a1), "r"(a2), "r"(a3), "r"(b0), "r"(b1));
}
__device__ __forceinline__ uint32_t cvt2(float hi, float lo) {
    uint32_t r;
    asm("cvt.rn.bf16x2.f32 %0, %1, %2;" : "=r"(r) : "f"(hi), "f"(lo));
    return r;
}
__device__ __forceinline__ uint32_t resid2(uint32_t h, float hi, float lo) {
    float fl = __uint_as_float(h << 16);
    float fh = __uint_as_float(h & 0xFFFF0000u);
    return cvt2(hi - fh, lo - fl);
}
__device__ __forceinline__ void cp16(uint32_t dst, const void* src) {
    asm volatile("cp.async.cg.shared.global [%0], [%1], 16;"
                 :: "r"(dst), "l"(__cvta_generic_to_global(src)));
}
#define CP_COMMIT() asm volatile("cp.async.commit_group;" ::: "memory")
#define CP_WAIT(N)  asm volatile("cp.async.wait_group %0;" :: "n"(N) : "memory")

// ================= Kernel 0: W transpose + bf16 split =================
__global__ __launch_bounds__(256) void prep_w_kernel(
    const float* __restrict__ Wk,
    const float* __restrict__ Wq,
    const float* __restrict__ Wv)
{
    int idx = (blockIdx.x * 256 + threadIdx.x) * 4;
    int w = idx >> 16;
    int r = idx & 65535;
    int n = r >> 10;
    int e = r & 1023;
    const float* W = (w == 0) ? Wk : (w == 1) ? Wq : Wv;
#pragma unroll
    for (int j = 0; j < 4; j++) {
        float v = W[(size_t)(e + j) * H_DIM + n];
        __nv_bfloat16 hi = __float2bfloat16(v);
        __nv_bfloat16 lo = __float2bfloat16(v - __bfloat162float(hi));
        g_wt_hi[idx + j] = hi;
        g_wt_lo[idx + j] = lo;
    }
}

// ================= Kernel 1: HMMA projection, cp.async pipelined ===========
// M=128/CTA (grid 128), 512 threads = 16 warps: (wid&7)->m16, (wid>>3)->n-half.
// A from global into registers (fp32->bf16 hi/lo), B double-buffered cp.async.
// B fragments via ldmatrix.x4 covering two n-tiles per load.
#define PROJ_STAGE_ELEMS (2 * 192 * KSTR)
#define PROJ_SMEM_BYTES  (2 * PROJ_STAGE_ELEMS * 2)   // 110592 B

__global__ __launch_bounds__(512, 1) void proj_mma_kernel(const float* __restrict__ x)
{
    __nv_bfloat16* sB = (__nv_bfloat16*)dynsmem;      // [stage][hi/lo][192][KSTR]
    const uint32_t b_u32 = smem_u32(sB);

    const int tid = threadIdx.x;
    const int wid = tid >> 5;
    const int lane = tid & 31;
    const int m0 = blockIdx.x * 128;
    const int wm = (wid & 7) * 16;
    const int wn = (wid >> 3) * 96;

    float acc[12][4];
#pragma unroll
    for (int nt = 0; nt < 12; nt++)
#pragma unroll
        for (int j = 0; j < 4; j++) acc[nt][j] = 0.0f;

    // X4 B-fragment lane offset: rows (lane>>4)*8 + (lane&7), kblk (lane>>3)&1
    const int bx4 = ((((lane >> 4) * 8 + (lane & 7))) * KSTR + ((lane >> 3) & 1) * 8) * 2;
    const int bn_off = wn * KSTR * 2;

    const int arow = m0 + wm + (lane >> 2);
    const float* xp0 = x + (size_t)arow * E_DIM + (lane & 3) * 2;
    const float* xp1 = xp0 + 8 * E_DIM;

    auto prefetchB = [&](int ch, int st) {
        const int e0 = ch * 32;
        const uint32_t dst0 = b_u32 + st * (PROJ_STAGE_ELEMS * 2);
#pragma unroll
        for (int it = 0; it < 3; it++) {
            int flat = it * 512 + tid;           // 0..1535
            int half = flat >= 768;
            int f = flat - half * 768;
            int n = f >> 2;
            int u = f & 3;
            const __nv_bfloat16* src = (half ? g_wt_lo : g_wt_hi) +
                                       (size_t)n * 1024 + e0 + u * 8;
            cp16(dst0 + (half * 192 * KSTR + n * KSTR + u * 8) * 2, src);
        }
    };
    auto loadA = [&](int ch, float2 r[2][4]) {
        const int e0 = ch * 32;
#pragma unroll
        for (int ks = 0; ks < 2; ks++) {
            int c = e0 + ks * 16;
            r[ks][0] = *(const float2*)&xp0[c];
            r[ks][1] = *(const float2*)&xp1[c];
            r[ks][2] = *(const float2*)&xp0[c + 8];
            r[ks][3] = *(const float2*)&xp1[c + 8];
        }
    };

    float2 curA[2][4], nextA[2][4];
    prefetchB(0, 0);
    CP_COMMIT();
    loadA(0, curA);

    for (int ch = 0; ch < 32; ch++) {
        const int st = ch & 1;
        if (ch + 1 < 32) loadA(ch + 1, nextA);
        __syncthreads();
        if (ch + 1 < 32) {
            prefetchB(ch + 1, st ^ 1);
            CP_COMMIT();
            CP_WAIT(1);
        } else {
            CP_WAIT(0);
        }
        __syncthreads();

        const uint32_t bh0a = b_u32 + st * (PROJ_STAGE_ELEMS * 2) + bn_off + bx4;
        const uint32_t bl0a = bh0a + 192 * KSTR * 2;
#pragma unroll
        for (int ks = 0; ks < 2; ks++) {
            uint32_t ah[4], al[4];
#pragma unroll
            for (int i = 0; i < 4; i++) {
                ah[i] = cvt2(curA[ks][i].y, curA[ks][i].x);
                al[i] = resid2(ah[i], curA[ks][i].y, curA[ks][i].x);
            }
#pragma unroll
            for (int nt2 = 0; nt2 < 6; nt2++) {
                const int off = nt2 * 16 * KSTR * 2 + ks * 32;
                uint32_t bh0, bh1, bh2, bh3, bl0, bl1, bl2, bl3;
                LDSM_X4(bh0, bh1, bh2, bh3, bh0a + off);
                LDSM_X4(bl0, bl1, bl2, bl3, bl0a + off);
                mma_bf16(acc[2 * nt2],     ah[0], ah[1], ah[2], ah[3], bh0, bh1);
                mma_bf16(acc[2 * nt2],     ah[0], ah[1], ah[2], ah[3], bl0, bl1);
                mma_bf16(acc[2 * nt2],     al[0], al[1], al[2], al[3], bh0, bh1);
                mma_bf16(acc[2 * nt2 + 1], ah[0], ah[1], ah[2], ah[3], bh2, bh3);
                mma_bf16(acc[2 * nt2 + 1], ah[0], ah[1], ah[2], ah[3], bl2, bl3);
                mma_bf16(acc[2 * nt2 + 1], al[0], al[1], al[2], al[3], bh2, bh3);
            }
        }
#pragma unroll
        for (int ks = 0; ks < 2; ks++)
#pragma unroll
            for (int i = 0; i < 4; i++) curA[ks][i] = nextA[ks][i];
    }

    // epilogue -> bf16 hi/lo q/k/v (q pre-scaled by 0.125)
    const int r0 = m0 + wm + (lane >> 2);
#pragma unroll
    for (int nt = 0; nt < 12; nt++) {
        int nglob = wn + nt * 8 + (lane & 3) * 2;
        int wsel = nglob >> 6;
        int col = nglob & 63;
        __nv_bfloat16 *oh, *ol;
        if (wsel == 0)      { oh = g_kh; ol = g_kl; }
        else if (wsel == 1) { oh = g_qh; ol = g_ql; }
        else                { oh = g_vh; ol = g_vl; }
        float sc = (wsel == 1) ? 0.125f : 1.0f;
        float v0 = acc[nt][0] * sc, v1 = acc[nt][1] * sc;
        float v2 = acc[nt][2] * sc, v3 = acc[nt][3] * sc;
        uint32_t h01 = cvt2(v1, v0);
        uint32_t l01 = resid2(h01, v1, v0);
        uint32_t h23 = cvt2(v3, v2);
        uint32_t l23 = resid2(h23, v3, v2);
        *(uint32_t*)&oh[(size_t)r0 * H_DIM + col] = h01;
        *(uint32_t*)&ol[(size_t)r0 * H_DIM + col] = l01;
        *(uint32_t*)&oh[(size_t)(r0 + 8) * H_DIM + col] = h23;
        *(uint32_t*)&ol[(size_t)(r0 + 8) * H_DIM + col] = l23;
    }
}

// ================= Kernel 2: HMMA split-K flash attention, pipelined =======
#define AT_ARR   (64 * KSTR)
#define AT_STAGE (4 * AT_ARR)
#define ATTN_SMEM_BYTES ((2 * QT * KSTR + 2 * AT_STAGE) * 2)   // 110592 B

__global__ __launch_bounds__(256, 2) void attn_kernel()
{
    __nv_bfloat16* sb = (__nv_bfloat16*)dynsmem;
    __nv_bfloat16* sQh = sb;                         // [128][KSTR]
    __nv_bfloat16* sQl = sb + QT * KSTR;
    __nv_bfloat16* kv0 = sb + 2 * QT * KSTR;         // [stage][kh|kl|vh|vl][64][KSTR]
    const uint32_t kv_u32 = smem_u32(kv0);

    const int tid = threadIdx.x;
    const int wid = tid >> 5;
    const int lane = tid & 31;
    const int b = blockIdx.y;

    int f = blockIdx.x;
    int qi = 0, pre = 0;
    while (pre + ((qi + 2) >> 1) <= f) { pre += (qi + 2) >> 1; qi++; }
    const int c = f - pre;
    const int nc = (qi + 2) >> 1;
    const int ntk = 2 * qi + 2;
    const int base = ntk / nc, rem = ntk % nc;
    const int my = base + (c < rem ? 1 : 0);
    const int start = c * base + (c < rem ? c : rem);
    const int q0 = qi * QT;

    auto prefetchKV = [&](int ki, int st) {
        const int n0 = ki * 64;
        const uint32_t dst0 = kv_u32 + st * (AT_STAGE * 2);
        const __nv_bfloat16* srcs[4] = {
            g_kh + ((size_t)b * T_DIM + n0) * H_DIM,
            g_kl + ((size_t)b * T_DIM + n0) * H_DIM,
            g_vh + ((size_t)b * T_DIM + n0) * H_DIM,
            g_vl + ((size_t)b * T_DIM + n0) * H_DIM };
#pragma unroll
        for (int it = 0; it < 8; it++) {
            int flat = it * 256 + tid;
            int arr = flat >> 9;
            int fr = flat & 511;
            int row = fr >> 3;
            int u = fr & 7;
            cp16(dst0 + (arr * AT_ARR + row * KSTR + u * 8) * 2,
                 srcs[arr] + (size_t)row * H_DIM + u * 8);
        }
    };

    prefetchKV(start, 0);
    CP_COMMIT();

    {
        const __nv_bfloat16* qh = g_qh + ((size_t)b * T_DIM + q0) * H_DIM;
        const __nv_bfloat16* ql = g_ql + ((size_t)b * T_DIM + q0) * H_DIM;
#pragma unroll
        for (int it = 0; it < 4; it++) {
            int flat = it * 256 + tid;
            int row = flat >> 3;
            int u = flat & 7;
            *(float4*)&sQh[row * KSTR + u * 8] = *(const float4*)&qh[(size_t)row * H_DIM + u * 8];
            *(float4*)&sQl[row * KSTR + u * 8] = *(const float4*)&ql[(size_t)row * H_DIM + u * 8];
        }
    }

    const int wm = wid * 16;
    const int amat = lane >> 3, ar = lane & 7;
    const int a_row = (amat & 1) * 8 + ar;
    const int a_kblk = (amat >> 1) * 8;
    uint32_t qh_base = smem_u32(sQh) + ((wm + a_row) * KSTR + a_kblk) * 2;
    uint32_t ql_base = smem_u32(sQl) + ((wm + a_row) * KSTR + a_kblk) * 2;
    // X4 K-fragment lane offset: rows (lane>>4)*8+(lane&7), kblk (lane>>3)&1
    const int kx4 = ((((lane >> 4) * 8 + (lane & 7))) * KSTR + ((lane >> 3) & 1) * 8) * 2;
    // X4 trans V-fragment lane offset: row t=(lane&15), col block (lane>>4)*8
    const int vx4 = ((lane & 15) * KSTR + (lane >> 4) * 8) * 2;

    __syncthreads();
    // hoist Q hi AND lo fragments (tile-invariant)
    uint32_t qfh[4][4], qfl[4][4];
#pragma unroll
    for (int ks = 0; ks < 4; ks++) {
        LDSM_X4(qfh[ks][0], qfh[ks][1], qfh[ks][2], qfh[ks][3], qh_base + ks * 32);
        LDSM_X4(qfl[ks][0], qfl[ks][1], qfl[ks][2], qfl[ks][3], ql_base + ks * 32);
    }

    float m0 = -1e30f, m1 = -1e30f, l0 = 0.0f, l1 = 0.0f;
    float o[8][4];
#pragma unroll
    for (int nt = 0; nt < 8; nt++)
#pragma unroll
        for (int j = 0; j < 4; j++) o[nt][j] = 0.0f;

    const int grow0 = q0 + wm + (lane >> 2);
    const int grow1 = grow0 + 8;

    for (int t = 0; t < my; t++) {
        const int st = t & 1;
        const int n0 = (start + t) * 64;
        __syncthreads();
        if (t + 1 < my) {
            prefetchKV(start + t + 1, st ^ 1);
            CP_COMMIT();
            CP_WAIT(1);
        } else {
            CP_WAIT(0);
        }
        __syncthreads();

        const uint32_t khb = kv_u32 + st * (AT_STAGE * 2) + kx4;
        const uint32_t klb = khb + AT_ARR * 2;
        const uint32_t vhb = kv_u32 + st * (AT_STAGE * 2) + 2 * AT_ARR * 2 + vx4;
        const uint32_t vlb = vhb + AT_ARR * 2;

        // ---- S = Q K^T ----
        float s[8][4];
#pragma unroll
        for (int nt = 0; nt < 8; nt++)
#pragma unroll
            for (int j = 0; j < 4; j++) s[nt][j] = 0.0f;

#pragma unroll
        for (int ks = 0; ks < 4; ks++) {
#pragma unroll
            for (int nt2 = 0; nt2 < 4; nt2++) {
                const int off = nt2 * 16 * KSTR * 2 + ks * 32;
                uint32_t bh0, bh1, bh2, bh3, bl0, bl1, bl2, bl3;
                LDSM_X4(bh0, bh1, bh2, bh3, khb + off);
                LDSM_X4(bl0, bl1, bl2, bl3, klb + off);
                mma_bf16(s[2 * nt2],     qfh[ks][0], qfh[ks][1], qfh[ks][2], qfh[ks][3], bh0, bh1);
                mma_bf16(s[2 * nt2],     qfh[ks][0], qfh[ks][1], qfh[ks][2], qfh[ks][3], bl0, bl1);
                mma_bf16(s[2 * nt2],     qfl[ks][0], qfl[ks][1], qfl[ks][2], qfl[ks][3], bh0, bh1);
                mma_bf16(s[2 * nt2 + 1], qfh[ks][0], qfh[ks][1], qfh[ks][2], qfh[ks][3], bh2, bh3);
                mma_bf16(s[2 * nt2 + 1], qfh[ks][0], qfh[ks][1], qfh[ks][2], qfh[ks][3], bl2, bl3);
                mma_bf16(s[2 * nt2 + 1], qfl[ks][0], qfl[ks][1], qfl[ks][2], qfl[ks][3], bh2, bh3);
            }
        }

        // ---- causal mask ----
        if (n0 + 63 > q0 + wm) {
#pragma unroll
            for (int nt = 0; nt < 8; nt++) {
                int cb = n0 + nt * 8 + (lane & 3) * 2;
                if (cb > grow0)     s[nt][0] = -1e30f;
                if (cb + 1 > grow0) s[nt][1] = -1e30f;
                if (cb > grow1)     s[nt][2] = -1e30f;
                if (cb + 1 > grow1) s[nt][3] = -1e30f;
            }
        }

        // ---- online softmax (2 rows per thread) ----
        {
            float rm = -1e30f;
#pragma unroll
            for (int nt = 0; nt < 8; nt++) rm = fmaxf(rm, fmaxf(s[nt][0], s[nt][1]));
            rm = fmaxf(rm, __shfl_xor_sync(0xffffffffu, rm, 1));
            rm = fmaxf(rm, __shfl_xor_sync(0xffffffffu, rm, 2));
            float mn = fmaxf(m0, rm);
            float al = __expf(m0 - mn);
            m0 = mn;
            float rs = 0.0f;
#pragma unroll
            for (int nt = 0; nt < 8; nt++) {
                s[nt][0] = __expf(s[nt][0] - mn);
                s[nt][1] = __expf(s[nt][1] - mn);
                rs += s[nt][0] + s[nt][1];
            }
            rs += __shfl_xor_sync(0xffffffffu, rs, 1);
            rs += __shfl_xor_sync(0xffffffffu, rs, 2);
            l0 = l0 * al + rs;
#pragma unroll
            for (int nt = 0; nt < 8; nt++) { o[nt][0] *= al; o[nt][1] *= al; }
        }
        {
            float rm = -1e30f;
#pragma unroll
            for (int nt = 0; nt < 8; nt++) rm = fmaxf(rm, fmaxf(s[nt][2], s[nt][3]));
            rm = fmaxf(rm, __shfl_xor_sync(0xffffffffu, rm, 1));
            rm = fmaxf(rm, __shfl_xor_sync(0xffffffffu, rm, 2));
            float mn = fmaxf(m1, rm);
            float al = __expf(m1 - mn);
            m1 = mn;
            float rs = 0.0f;
#pragma unroll
            for (int nt = 0; nt < 8; nt++) {
                s[nt][2] = __expf(s[nt][2] - mn);
                s[nt][3] = __expf(s[nt][3] - mn);
                rs += s[nt][2] + s[nt][3];
            }
            rs += __shfl_xor_sync(0xffffffffu, rs, 1);
            rs += __shfl_xor_sync(0xffffffffu, rs, 2);
            l1 = l1 * al + rs;
#pragma unroll
            for (int nt = 0; nt < 8; nt++) { o[nt][2] *= al; o[nt][3] *= al; }
        }

        // ---- O += P V ----
#pragma unroll
        for (int ks = 0; ks < 4; ks++) {
            uint32_t ph0 = cvt2(s[2 * ks][1],     s[2 * ks][0]);
            uint32_t ph1 = cvt2(s[2 * ks][3],     s[2 * ks][2]);
            uint32_t ph2 = cvt2(s[2 * ks + 1][1], s[2 * ks + 1][0]);
            uint32_t ph3 = cvt2(s[2 * ks + 1][3], s[2 * ks + 1][2]);
            uint32_t pl0 = resid2(ph0, s[2 * ks][1],     s[2 * ks][0]);
            uint32_t pl1 = resid2(ph1, s[2 * ks][3],     s[2 * ks][2]);
            uint32_t pl2 = resid2(ph2, s[2 * ks + 1][1], s[2 * ks + 1][0]);
            uint32_t pl3 = resid2(ph3, s[2 * ks + 1][3], s[2 * ks + 1][2]);
            const int tko = ks * 16 * KSTR * 2;
#pragma unroll
            for (int nt2 = 0; nt2 < 4; nt2++) {
                const int off = tko + nt2 * 32;
                uint32_t vh0, vh1, vh2, vh3, vl0, vl1, vl2, vl3;
                LDSM_X4_T(vh0, vh1, vh2, vh3, vhb + off);
                LDSM_X4_T(vl0, vl1, vl2, vl3, vlb + off);
                mma_bf16(o[2 * nt2],     ph0, ph1, ph2, ph3, vh0, vh1);
                mma_bf16(o[2 * nt2],     ph0, ph1, ph2, ph3, vl0, vl1);
                mma_bf16(o[2 * nt2],     pl0, pl1, pl2, pl3, vh0, vh1);
                mma_bf16(o[2 * nt2 + 1], ph0, ph1, ph2, ph3, vh2, vh3);
                mma_bf16(o[2 * nt2 + 1], ph0, ph1, ph2, ph3, vl2, vl3);
                mma_bf16(o[2 * nt2 + 1], pl0, pl1, pl2, pl3, vh2, vh3);
            }
        }
    }

    // ---- write partial (unnormalized O, m, l) ----
    const size_t pb = (size_t)(b * NQT2 + qi) * MAXC2 + c;
    float* pO = g_pO + pb * (QT * H_DIM);
    const int r0 = wm + (lane >> 2);
    const int cb = (lane & 3) * 2;
#pragma unroll
    for (int nt = 0; nt < 8; nt++) {
        *(float2*)&pO[(r0)     * H_DIM + nt * 8 + cb] = make_float2(o[nt][0], o[nt][1]);
        *(float2*)&pO[(r0 + 8) * H_DIM + nt * 8 + cb] = make_float2(o[nt][2], o[nt][3]);
    }
    if ((lane & 3) == 0) {
        g_pm[pb * QT + r0] = m0;     g_pl[pb * QT + r0] = l0;
        g_pm[pb * QT + r0 + 8] = m1; g_pl[pb * QT + r0 + 8] = l1;
    }
}

// ================= Kernel 3: combine partials =================
// Grid (NQT2*8, B): block handles 16 rows; thread = (row, 4 cols).
__global__ __launch_bounds__(256) void combine_kernel(float* __restrict__ out)
{
    const int qi = blockIdx.x >> 3;
    const int oct = blockIdx.x & 7;
    const int b = blockIdx.y;
    const int nc = (qi + 2) >> 1;
    const int tid = threadIdx.x;
    const int row = oct * 16 + (tid >> 4);
    const int cg = (tid & 15) * 4;

    const size_t pb0 = (size_t)(b * NQT2 + qi) * MAXC2;

    float mg = -1e30f;
    for (int c = 0; c < nc; c++)
        mg = fmaxf(mg, g_pm[(pb0 + c) * QT + row]);

    float lg = 0.0f;
    for (int c = 0; c < nc; c++)
        lg += g_pl[(pb0 + c) * QT + row] * __expf(g_pm[(pb0 + c) * QT + row] - mg);
    float inv = 1.0f / lg;

    float4 a0 = make_float4(0.f, 0.f, 0.f, 0.f);

    for (int c = 0; c < nc; c++) {
        float w = __expf(g_pm[(pb0 + c) * QT + row] - mg);
        const float* pO = g_pO + (pb0 + c) * (QT * H_DIM) + row * H_DIM + cg;
        float4 t0 = *(const float4*)&pO[0];
        a0.x += w * t0.x; a0.y += w * t0.y; a0.z += w * t0.z; a0.w += w * t0.w;
    }

    float* o = out + ((size_t)b * T_DIM + qi * QT + row) * H_DIM + cg;
    *(float4*)&o[0] = make_float4(a0.x * inv, a0.y * inv, a0.z * inv, a0.w * inv);
}

extern "C" void kernel_launch(void* const* d_in, const int* in_sizes, int n_in,
                              void* d_out, int out_size)
{
    (void)in_sizes; (void)n_in; (void)out_size;
    const float* x  = (const float*)d_in[0];
    const float* Wk = (const float*)d_in[1];
    const float* Wq = (const float*)d_in[2];
    const float* Wv = (const float*)d_in[3];
    float* out = (float*)d_out;

    static bool attr_set = false;
    if (!attr_set) {
        cudaFuncSetAttribute(attn_kernel,
                             cudaFuncAttributeMaxDynamicSharedMemorySize,
                             ATTN_SMEM_BYTES);
        cudaFuncSetAttribute(proj_mma_kernel,
                             cudaFuncAttributeMaxDynamicSharedMemorySize,
                             PROJ_SMEM_BYTES);
        attr_set = true;
    }

    prep_w_kernel<<<192, 256>>>(Wk, Wq, Wv);
    proj_mma_kernel<<<M_DIM / 128, 512, PROJ_SMEM_BYTES>>>(x);
    attn_kernel<<<dim3(CH2_PER_B, B_DIM), 256, ATTN_SMEM_BYTES>>>();
    combine_kernel<<<dim3(NQT2 * 8, B_DIM), 256>>>(out);
}